// round 2
// baseline (speedup 1.0000x reference)
#include <cuda_runtime.h>
#include <math.h>
#include <stdint.h>

// Problem constants
#define B_    4
#define NC_   4096
#define NS_   1024
#define CD_   1024
#define SD_   768
#define H_    16
#define D_    64
#define INNER_ 1024
#define LN_EPS 1e-5f

// ---------------- static device scratch (no runtime allocation) ----------------
__device__ float g_q[(size_t)B_ * NC_ * INNER_];        // 64 MB  [b*NC+q][h*64+d]
__device__ float g_k[(size_t)B_ * NS_ * INNER_];        // 16 MB  [b*NS+s][h*64+d]
__device__ float g_v[(size_t)B_ * NS_ * INNER_];        // 16 MB
__device__ float g_attn[(size_t)B_ * H_ * NC_ * NS_];   // 1 GB   [(b*16+h)*NC+q][k]
__device__ float g_av[(size_t)B_ * NC_ * INNER_];       // 64 MB  [b*NC+q][h*64+d]
__device__ float g_x[(size_t)B_ * NC_ * CD_];           // 64 MB  pre-LN residual sum

// ================================================================
// Generic SGEMM: C[M,N] = A[M,K] @ B[K,N]  (+ bias[N] + resid[M,N])
// 128x128 block tile, BK=8, 256 threads, 8x8 per thread.
// ================================================================
__global__ void sgemm_nn(const float* __restrict__ A, const float* __restrict__ B,
                         float* __restrict__ C, int M, int N, int K,
                         const float* __restrict__ bias,
                         const float* __restrict__ resid)
{
    __shared__ float As[8][128];
    __shared__ float Bs[8][128];

    const int bm = blockIdx.y * 128;
    const int bn = blockIdx.x * 128;
    const int tid = threadIdx.x;
    const int ty = tid >> 4;       // 0..15
    const int tx = tid & 15;       // 0..15

    const int arow = tid >> 1;           // 0..127
    const int acol = (tid & 1) << 2;     // 0 or 4
    const int brow = tid >> 5;           // 0..7
    const int bcol = (tid & 31) << 2;    // 0..124

    float acc[8][8];
#pragma unroll
    for (int i = 0; i < 8; i++)
#pragma unroll
        for (int j = 0; j < 8; j++) acc[i][j] = 0.f;

    const float* Abase = A + (size_t)(bm + arow) * K;

    for (int k0 = 0; k0 < K; k0 += 8) {
        float4 a = *(const float4*)(Abase + k0 + acol);
        As[acol + 0][arow] = a.x;
        As[acol + 1][arow] = a.y;
        As[acol + 2][arow] = a.z;
        As[acol + 3][arow] = a.w;
        float4 b = *(const float4*)(B + (size_t)(k0 + brow) * N + bn + bcol);
        *(float4*)&Bs[brow][bcol] = b;
        __syncthreads();

#pragma unroll
        for (int kk = 0; kk < 8; kk++) {
            float ar[8], br[8];
#pragma unroll
            for (int i = 0; i < 8; i++) ar[i] = As[kk][ty * 8 + i];
#pragma unroll
            for (int j = 0; j < 8; j++) br[j] = Bs[kk][tx * 8 + j];
#pragma unroll
            for (int i = 0; i < 8; i++)
#pragma unroll
                for (int j = 0; j < 8; j++) acc[i][j] = fmaf(ar[i], br[j], acc[i][j]);
        }
        __syncthreads();
    }

#pragma unroll
    for (int i = 0; i < 8; i++) {
        const int m = bm + ty * 8 + i;
#pragma unroll
        for (int j4 = 0; j4 < 8; j4 += 4) {
            const int n = bn + tx * 8 + j4;
            float4 r = make_float4(acc[i][j4], acc[i][j4 + 1], acc[i][j4 + 2], acc[i][j4 + 3]);
            if (bias) {
                r.x += bias[n + 0]; r.y += bias[n + 1];
                r.z += bias[n + 2]; r.w += bias[n + 3];
            }
            if (resid) {
                float4 t = *(const float4*)(resid + (size_t)m * N + n);
                r.x += t.x; r.y += t.y; r.z += t.z; r.w += t.w;
            }
            *(float4*)(C + (size_t)m * N + n) = r;
        }
    }
}

// ================================================================
// Scores: S[b,h,q,k] = scale * sum_d Q[b,q,h,d] * K[b,k,h,d]
// grid: (NS/128, NC/128, B*H)
// ================================================================
__global__ void scores_kernel()
{
    __shared__ float Qs[32][128];
    __shared__ float Ks[32][128];

    const int z = blockIdx.z;             // b*16 + h
    const int b = z >> 4;
    const int h = z & 15;
    const int qbase = b * NC_ + blockIdx.y * 128;
    const int kbase = b * NS_ + blockIdx.x * 128;
    const int hoff = h * 64;
    const int tid = threadIdx.x;
    const int ty = tid >> 4;
    const int tx = tid & 15;

    float acc[8][8];
#pragma unroll
    for (int i = 0; i < 8; i++)
#pragma unroll
        for (int j = 0; j < 8; j++) acc[i][j] = 0.f;

    for (int k0 = 0; k0 < 64; k0 += 32) {
        for (int i = tid; i < 1024; i += 256) {
            const int row = i >> 3;             // 0..127
            const int c4  = (i & 7) << 2;       // 0..28
            float4 q4 = *(const float4*)(g_q + (size_t)(qbase + row) * INNER_ + hoff + k0 + c4);
            Qs[c4 + 0][row] = q4.x; Qs[c4 + 1][row] = q4.y;
            Qs[c4 + 2][row] = q4.z; Qs[c4 + 3][row] = q4.w;
            float4 k4 = *(const float4*)(g_k + (size_t)(kbase + row) * INNER_ + hoff + k0 + c4);
            Ks[c4 + 0][row] = k4.x; Ks[c4 + 1][row] = k4.y;
            Ks[c4 + 2][row] = k4.z; Ks[c4 + 3][row] = k4.w;
        }
        __syncthreads();

#pragma unroll
        for (int kk = 0; kk < 32; kk++) {
            float ar[8], br[8];
#pragma unroll
            for (int i = 0; i < 8; i++) ar[i] = Qs[kk][ty * 8 + i];
#pragma unroll
            for (int j = 0; j < 8; j++) br[j] = Ks[kk][tx * 8 + j];
#pragma unroll
            for (int i = 0; i < 8; i++)
#pragma unroll
                for (int j = 0; j < 8; j++) acc[i][j] = fmaf(ar[i], br[j], acc[i][j]);
        }
        __syncthreads();
    }

    const float scale = 0.125f;   // 64^-0.5
    const size_t zofs = (size_t)z << 22;  // z * NC_ * NS_
#pragma unroll
    for (int i = 0; i < 8; i++) {
        const size_t row = (size_t)(blockIdx.y * 128 + ty * 8 + i);
#pragma unroll
        for (int j4 = 0; j4 < 8; j4 += 4) {
            const int col = blockIdx.x * 128 + tx * 8 + j4;
            float4 r = make_float4(acc[i][j4] * scale, acc[i][j4 + 1] * scale,
                                   acc[i][j4 + 2] * scale, acc[i][j4 + 3] * scale);
            *(float4*)(g_attn + zofs + row * NS_ + col) = r;
        }
    }
}

// ================================================================
// Row softmax over NS=1024, in place. grid = B*H*NC rows, 256 thr.
// ================================================================
__global__ void softmax_kernel()
{
    __shared__ float red[9];
    const size_t row = blockIdx.x;
    float* p = g_attn + row * NS_;
    const int tid = threadIdx.x;

    float4 v = reinterpret_cast<float4*>(p)[tid];
    float m = fmaxf(fmaxf(v.x, v.y), fmaxf(v.z, v.w));
#pragma unroll
    for (int o = 16; o; o >>= 1) m = fmaxf(m, __shfl_xor_sync(0xffffffffu, m, o));
    if ((tid & 31) == 0) red[tid >> 5] = m;
    __syncthreads();
    if (tid == 0) {
        float mm = red[0];
#pragma unroll
        for (int i = 1; i < 8; i++) mm = fmaxf(mm, red[i]);
        red[8] = mm;
    }
    __syncthreads();
    m = red[8];
    __syncthreads();

    v.x = __expf(v.x - m); v.y = __expf(v.y - m);
    v.z = __expf(v.z - m); v.w = __expf(v.w - m);
    float s = v.x + v.y + v.z + v.w;
#pragma unroll
    for (int o = 16; o; o >>= 1) s += __shfl_xor_sync(0xffffffffu, s, o);
    if ((tid & 31) == 0) red[tid >> 5] = s;
    __syncthreads();
    if (tid == 0) {
        float ss = 0.f;
#pragma unroll
        for (int i = 0; i < 8; i++) ss += red[i];
        red[8] = 1.f / ss;
    }
    __syncthreads();
    const float inv = red[8];
    v.x *= inv; v.y *= inv; v.z *= inv; v.w *= inv;
    reinterpret_cast<float4*>(p)[tid] = v;
}

// ================================================================
// attn_mean[b,q,k] = (1/16) * sum_h attn[b,h,q,k]  -> d_out 2nd half
// ================================================================
__global__ void attn_mean_kernel(float* __restrict__ out2)
{
    const size_t idx = (size_t)blockIdx.x * 256 + threadIdx.x;  // < B*NC*NS
    const int b = (int)(idx >> 22);              // / (NC*NS)
    const size_t r = idx & ((1u << 22) - 1);
    float s = 0.f;
#pragma unroll
    for (int h = 0; h < H_; h++)
        s += g_attn[(((size_t)(b * H_ + h)) << 22) + r];
    out2[idx] = s * (1.0f / 16.0f);
}

// ================================================================
// AV: av[b,q,h,d] = sum_k attn[b,h,q,k] * V[b,k,h,d]
// grid: (1, NC/128, B*H)
// ================================================================
__global__ void av_kernel()
{
    __shared__ float Ps[16][128];
    __shared__ float Vs[16][64];

    const int z = blockIdx.z;
    const int b = z >> 4;
    const int h = z & 15;
    const int by = blockIdx.y;
    const int hoff = h * 64;
    const int tid = threadIdx.x;
    const int ty = tid >> 4;
    const int tx = tid & 15;
    const size_t zofs = (size_t)z << 22;

    float acc[8][4];
#pragma unroll
    for (int i = 0; i < 8; i++)
#pragma unroll
        for (int j = 0; j < 4; j++) acc[i][j] = 0.f;

    for (int k0 = 0; k0 < NS_; k0 += 16) {
        for (int i = tid; i < 512; i += 256) {
            const int row = i >> 2;            // 0..127
            const int c4  = (i & 3) << 2;      // 0..12
            float4 p4 = *(const float4*)(g_attn + zofs + (size_t)(by * 128 + row) * NS_ + k0 + c4);
            Ps[c4 + 0][row] = p4.x; Ps[c4 + 1][row] = p4.y;
            Ps[c4 + 2][row] = p4.z; Ps[c4 + 3][row] = p4.w;
        }
        {
            const int row = tid >> 4;          // 0..15
            const int c4  = (tid & 15) << 2;   // 0..60
            float4 v4 = *(const float4*)(g_v + (size_t)(b * NS_ + k0 + row) * INNER_ + hoff + c4);
            *(float4*)&Vs[row][c4] = v4;
        }
        __syncthreads();

#pragma unroll
        for (int kk = 0; kk < 16; kk++) {
            float ar[8], br[4];
#pragma unroll
            for (int i = 0; i < 8; i++) ar[i] = Ps[kk][ty * 8 + i];
#pragma unroll
            for (int j = 0; j < 4; j++) br[j] = Vs[kk][tx * 4 + j];
#pragma unroll
            for (int i = 0; i < 8; i++)
#pragma unroll
                for (int j = 0; j < 4; j++) acc[i][j] = fmaf(ar[i], br[j], acc[i][j]);
        }
        __syncthreads();
    }

#pragma unroll
    for (int i = 0; i < 8; i++) {
        const size_t row = (size_t)(b * NC_ + by * 128 + ty * 8 + i);
        float4 r = make_float4(acc[i][0], acc[i][1], acc[i][2], acc[i][3]);
        *(float4*)(g_av + row * INNER_ + hoff + tx * 4) = r;
    }
}

// ================================================================
// LayerNorm rows of g_x (len 1024) -> d_out first half
// ================================================================
__global__ void ln_kernel(const float* __restrict__ gamma,
                          const float* __restrict__ beta,
                          float* __restrict__ out)
{
    __shared__ float reds[9];
    __shared__ float redq[9];
    const size_t row = blockIdx.x;
    const int tid = threadIdx.x;

    float4 x = reinterpret_cast<const float4*>(g_x + row * CD_)[tid];
    float s = x.x + x.y + x.z + x.w;
    float q = x.x * x.x + x.y * x.y + x.z * x.z + x.w * x.w;
#pragma unroll
    for (int o = 16; o; o >>= 1) {
        s += __shfl_xor_sync(0xffffffffu, s, o);
        q += __shfl_xor_sync(0xffffffffu, q, o);
    }
    if ((tid & 31) == 0) { reds[tid >> 5] = s; redq[tid >> 5] = q; }
    __syncthreads();
    if (tid == 0) {
        float ss = 0.f, qq = 0.f;
#pragma unroll
        for (int i = 0; i < 8; i++) { ss += reds[i]; qq += redq[i]; }
        reds[8] = ss; redq[8] = qq;
    }
    __syncthreads();
    const float mu = reds[8] * (1.0f / 1024.0f);
    const float var = redq[8] * (1.0f / 1024.0f) - mu * mu;
    const float rstd = rsqrtf(var + LN_EPS);

    float4 g = reinterpret_cast<const float4*>(gamma)[tid];
    float4 bb = reinterpret_cast<const float4*>(beta)[tid];
    float4 r;
    r.x = (x.x - mu) * rstd * g.x + bb.x;
    r.y = (x.y - mu) * rstd * g.y + bb.y;
    r.z = (x.z - mu) * rstd * g.z + bb.z;
    r.w = (x.w - mu) * rstd * g.w + bb.w;
    reinterpret_cast<float4*>(out + row * CD_)[tid] = r;
}

// ================================================================
extern "C" void kernel_launch(void* const* d_in, const int* in_sizes, int n_in,
                              void* d_out, int out_size)
{
    const float* content = (const float*)d_in[0];  // [4,4096,1024]
    const float* style   = (const float*)d_in[1];  // [4,1024,768]
    const float* Wq      = (const float*)d_in[2];  // [1024,1024]
    const float* Wk      = (const float*)d_in[3];  // [768,1024]
    const float* Wv      = (const float*)d_in[4];  // [768,1024]
    const float* Wo      = (const float*)d_in[5];  // [1024,1024]
    const float* bo      = (const float*)d_in[6];  // [1024]
    const float* gamma   = (const float*)d_in[7];  // [1024]
    const float* beta    = (const float*)d_in[8];  // [1024]
    float* out = (float*)d_out;
    float* out_attn = out + (size_t)B_ * NC_ * CD_;

    // Resolve REAL device addresses of the __device__ scratch symbols.
    // (Passing the symbol name directly from host code passes the host
    // shadow address — on GB300 ATS that silently reads/writes host RAM.)
    float *p_q, *p_k, *p_v, *p_av, *p_x;
    cudaGetSymbolAddress((void**)&p_q,  g_q);
    cudaGetSymbolAddress((void**)&p_k,  g_k);
    cudaGetSymbolAddress((void**)&p_v,  g_v);
    cudaGetSymbolAddress((void**)&p_av, g_av);
    cudaGetSymbolAddress((void**)&p_x,  g_x);

    // 1) Q = content @ Wq    [16384,1024]
    {
        dim3 grid(INNER_ / 128, (B_ * NC_) / 128);
        sgemm_nn<<<grid, 256>>>(content, Wq, p_q, B_ * NC_, INNER_, CD_, nullptr, nullptr);
    }
    // 2) K,V = style @ Wk / Wv   [4096,1024]
    {
        dim3 grid(INNER_ / 128, (B_ * NS_) / 128);
        sgemm_nn<<<grid, 256>>>(style, Wk, p_k, B_ * NS_, INNER_, SD_, nullptr, nullptr);
        sgemm_nn<<<grid, 256>>>(style, Wv, p_v, B_ * NS_, INNER_, SD_, nullptr, nullptr);
    }
    // 3) scores
    {
        dim3 grid(NS_ / 128, NC_ / 128, B_ * H_);
        scores_kernel<<<grid, 256>>>();
    }
    // 4) softmax in place
    softmax_kernel<<<B_ * H_ * NC_, 256>>>();
    // 5) head-mean of attention -> second output
    attn_mean_kernel<<<(B_ * NC_ * NS_) / 256, 256>>>(out_attn);
    // 6) av = attn @ V
    {
        dim3 grid(1, NC_ / 128, B_ * H_);
        av_kernel<<<grid, 256>>>();
    }
    // 7) x = av @ Wo + bo + content
    {
        dim3 grid(CD_ / 128, (B_ * NC_) / 128);
        sgemm_nn<<<grid, 256>>>(p_av, Wo, p_x, B_ * NC_, CD_, INNER_, bo, content);
    }
    // 8) LayerNorm -> first output
    ln_kernel<<<B_ * NC_, 256>>>(gamma, beta, out);
}

// round 4
// speedup vs baseline: 1.3861x; 1.3861x over previous
#include <cuda_runtime.h>
#include <cuda_bf16.h>
#include <math.h>
#include <stdint.h>

// Problem constants
#define B_    4
#define NC_   4096
#define NS_   1024
#define CD_   1024
#define SD_   768
#define H_    16
#define D_    64
#define INNER_ 1024
#define LN_EPS 1e-5f

// ---------------- static device scratch (no runtime allocation) ----------------
__device__ float g_q[(size_t)B_ * NC_ * INNER_];        // 64 MB
__device__ float g_k[(size_t)B_ * NS_ * INNER_];        // 16 MB
__device__ float g_v[(size_t)B_ * NS_ * INNER_];        // 16 MB
__device__ float g_attn[(size_t)B_ * H_ * NC_ * NS_];   // 1 GB
__device__ float g_x[(size_t)B_ * NC_ * CD_];           // 64 MB

// bf16 hi/lo split operands for tensor-core GEMMs
__device__ __nv_bfloat16 g_c_hi[(size_t)B_ * NC_ * CD_];
__device__ __nv_bfloat16 g_c_lo[(size_t)B_ * NC_ * CD_];
__device__ __nv_bfloat16 g_s_hi[(size_t)B_ * NS_ * SD_];
__device__ __nv_bfloat16 g_s_lo[(size_t)B_ * NS_ * SD_];
__device__ __nv_bfloat16 g_avh[(size_t)B_ * NC_ * INNER_];
__device__ __nv_bfloat16 g_avl[(size_t)B_ * NC_ * INNER_];
// transposed weights [N][K]
__device__ __nv_bfloat16 g_wqt_hi[INNER_ * CD_];
__device__ __nv_bfloat16 g_wqt_lo[INNER_ * CD_];
__device__ __nv_bfloat16 g_wkt_hi[INNER_ * SD_];
__device__ __nv_bfloat16 g_wkt_lo[INNER_ * SD_];
__device__ __nv_bfloat16 g_wvt_hi[INNER_ * SD_];
__device__ __nv_bfloat16 g_wvt_lo[INNER_ * SD_];
__device__ __nv_bfloat16 g_wot_hi[CD_ * INNER_];
__device__ __nv_bfloat16 g_wot_lo[CD_ * INNER_];

// ================= helpers =================
__device__ __forceinline__ uint32_t smem_u32(const void* p) {
    uint32_t a;
    asm("{ .reg .u64 t; cvta.to.shared.u64 t, %1; cvt.u32.u64 %0, t; }" : "=r"(a) : "l"(p));
    return a;
}
__device__ __forceinline__ void ldsm_x4(uint32_t* f, uint32_t addr) {
    asm volatile("ldmatrix.sync.aligned.m8n8.x4.shared.b16 {%0,%1,%2,%3}, [%4];"
                 : "=r"(f[0]), "=r"(f[1]), "=r"(f[2]), "=r"(f[3]) : "r"(addr));
}
__device__ __forceinline__ void ldsm_x2(uint32_t* f, uint32_t addr) {
    asm volatile("ldmatrix.sync.aligned.m8n8.x2.shared.b16 {%0,%1}, [%2];"
                 : "=r"(f[0]), "=r"(f[1]) : "r"(addr));
}
__device__ __forceinline__ void mma_bf16(float* c, const uint32_t* a, const uint32_t* b) {
    asm volatile("mma.sync.aligned.m16n8k16.row.col.f32.bf16.bf16.f32 "
                 "{%0,%1,%2,%3}, {%4,%5,%6,%7}, {%8,%9}, {%0,%1,%2,%3};"
                 : "+f"(c[0]), "+f"(c[1]), "+f"(c[2]), "+f"(c[3])
                 : "r"(a[0]), "r"(a[1]), "r"(a[2]), "r"(a[3]), "r"(b[0]), "r"(b[1]));
}

// ================================================================
// Warp-MMA bf16-split GEMM: C[M,N] = (Ah+Al)[M,K] @ (Bh+Bl)[N,K]^T
//   3-term split: Ah*Bh + Ah*Bl + Al*Bh  (fp32-class accuracy)
// 128x128 CTA tile, BK=32 bf16, 256 threads = 8 warps (2x4), 64x32/warp.
// smem: 2 buffers x 4 tiles x [128 rows x 40 bf16 (80B, padded)] = 80 KB.
// ================================================================
#define TILE_B   10240           // one 128x40 bf16 tile, bytes
#define BUF_B    (4 * TILE_B)    // 40960
#define GSMEM_B  (2 * BUF_B)     // 81920

__global__ void __launch_bounds__(256, 1) gemm_mma(
    const __nv_bfloat16* __restrict__ Ah, const __nv_bfloat16* __restrict__ Al,
    const __nv_bfloat16* __restrict__ Bh, const __nv_bfloat16* __restrict__ Bl,
    float* __restrict__ C, int M, int N, int K,
    const float* __restrict__ bias, const float* __restrict__ resid)
{
    extern __shared__ char sm[];
    const int tid = threadIdx.x;
    const int lane = tid & 31;
    const int wid = tid >> 5;
    const int bm = blockIdx.y * 128;
    const int bn = blockIdx.x * 128;
    const int nch = K >> 5;      // chunks of 32

    const int wm = (wid >> 2) * 64;   // 0 / 64
    const int wn = (wid & 3) * 32;    // 0..96

    const uint32_t sA = smem_u32(sm);
    // ldmatrix per-lane offsets (within a tile)
    const uint32_t a_off = (uint32_t)(lane & 15) * 80 + (uint32_t)(lane >> 4) * 16;
    const uint32_t b_off = (uint32_t)(lane & 7) * 80 + (uint32_t)((lane >> 3) & 1) * 16;

    float acc[4][4][4];
#pragma unroll
    for (int mt = 0; mt < 4; mt++)
#pragma unroll
        for (int nt = 0; nt < 4; nt++)
#pragma unroll
            for (int r = 0; r < 4; r++) acc[mt][nt][r] = 0.f;

    // ---- prologue: load chunk 0 into buffer 0 ----
#pragma unroll
    for (int it = 0; it < 8; it++) {
        const int idx = (it << 8) + tid;
        const int t = idx >> 9;             // 0..3
        const int r = (idx >> 2) & 127;
        const int s = idx & 3;
        const __nv_bfloat16* src = (t == 0) ? Ah : (t == 1) ? Al : (t == 2) ? Bh : Bl;
        const int rb = (t < 2) ? bm : bn;
        uint4 v = *(const uint4*)(src + (size_t)(rb + r) * K + s * 8);
        *(uint4*)(sm + t * TILE_B + r * 80 + s * 16) = v;
    }
    __syncthreads();

    for (int c = 0; c < nch; c++) {
        // issue next chunk's global loads
        uint4 g[8];
        if (c + 1 < nch) {
            const int ko = (c + 1) << 5;
#pragma unroll
            for (int it = 0; it < 8; it++) {
                const int idx = (it << 8) + tid;
                const int t = idx >> 9;
                const int r = (idx >> 2) & 127;
                const int s = idx & 3;
                const __nv_bfloat16* src = (t == 0) ? Ah : (t == 1) ? Al : (t == 2) ? Bh : Bl;
                const int rb = (t < 2) ? bm : bn;
                g[it] = *(const uint4*)(src + (size_t)(rb + r) * K + ko + s * 8);
            }
        }

        // compute on buffer c&1
        {
            const uint32_t base = sA + (uint32_t)(c & 1) * BUF_B;
            const uint32_t bAh = base;
            const uint32_t bAl = base + TILE_B;
            const uint32_t bBh = base + 2 * TILE_B;
            const uint32_t bBl = base + 3 * TILE_B;
#pragma unroll
            for (int kk = 0; kk < 2; kk++) {
                const uint32_t ko = kk * 32;   // 16 bf16 = 32 bytes
                uint32_t bh[4][2], bl[4][2];
#pragma unroll
                for (int nt = 0; nt < 4; nt++) {
                    ldsm_x2(bh[nt], bBh + (uint32_t)(wn + nt * 8) * 80 + b_off + ko);
                    ldsm_x2(bl[nt], bBl + (uint32_t)(wn + nt * 8) * 80 + b_off + ko);
                }
#pragma unroll
                for (int mt = 0; mt < 4; mt++) {
                    uint32_t ah[4], al[4];
                    ldsm_x4(ah, bAh + (uint32_t)(wm + mt * 16) * 80 + a_off + ko);
                    ldsm_x4(al, bAl + (uint32_t)(wm + mt * 16) * 80 + a_off + ko);
#pragma unroll
                    for (int nt = 0; nt < 4; nt++) {
                        mma_bf16(acc[mt][nt], ah, bh[nt]);
                        mma_bf16(acc[mt][nt], ah, bl[nt]);
                        mma_bf16(acc[mt][nt], al, bh[nt]);
                    }
                }
            }
        }

        // store next chunk into other buffer
        if (c + 1 < nch) {
            char* dst = sm + ((c + 1) & 1) * BUF_B;
#pragma unroll
            for (int it = 0; it < 8; it++) {
                const int idx = (it << 8) + tid;
                const int t = idx >> 9;
                const int r = (idx >> 2) & 127;
                const int s = idx & 3;
                *(uint4*)(dst + t * TILE_B + r * 80 + s * 16) = g[it];
            }
        }
        __syncthreads();
    }

    // ---- epilogue ----
#pragma unroll
    for (int mt = 0; mt < 4; mt++) {
        const int row0 = bm + wm + mt * 16 + (lane >> 2);
#pragma unroll
        for (int nt = 0; nt < 4; nt++) {
            const int col = bn + wn + nt * 8 + (lane & 3) * 2;
#pragma unroll
            for (int half = 0; half < 2; half++) {
                const int row = row0 + half * 8;
                float2 v = make_float2(acc[mt][nt][half * 2], acc[mt][nt][half * 2 + 1]);
                if (bias) { v.x += bias[col]; v.y += bias[col + 1]; }
                if (resid) {
                    float2 t = *(const float2*)(resid + (size_t)row * N + col);
                    v.x += t.x; v.y += t.y;
                }
                *(float2*)(C + (size_t)row * N + col) = v;
            }
        }
    }
}

// ================================================================
// fp32 -> bf16 hi/lo split (vectorized)
// ================================================================
__global__ void split_kernel(const float4* __restrict__ in,
                             uint2* __restrict__ oh, uint2* __restrict__ ol, int n4)
{
    const int i = blockIdx.x * 256 + threadIdx.x;
    if (i >= n4) return;
    float4 v = in[i];
    __align__(8) __nv_bfloat16 h[4], l[4];
    const float f[4] = {v.x, v.y, v.z, v.w};
#pragma unroll
    for (int j = 0; j < 4; j++) {
        h[j] = __float2bfloat16(f[j]);
        l[j] = __float2bfloat16(f[j] - __bfloat162float(h[j]));
    }
    oh[i] = *(uint2*)h;
    ol[i] = *(uint2*)l;
}

// ================================================================
// Transpose + split: fp32 [R][Ncol] -> bf16 [Ncol][R] hi/lo
// ================================================================
__global__ void tsplit_kernel(const float* __restrict__ in,
                              __nv_bfloat16* __restrict__ oh,
                              __nv_bfloat16* __restrict__ ol, int R, int Ncol)
{
    __shared__ float t[32][33];
    const int bx = blockIdx.x * 32, by = blockIdx.y * 32;
    const int tx = threadIdx.x, ty = threadIdx.y;
#pragma unroll
    for (int i = 0; i < 32; i += 8)
        t[ty + i][tx] = in[(size_t)(by + ty + i) * Ncol + bx + tx];
    __syncthreads();
#pragma unroll
    for (int i = 0; i < 32; i += 8) {
        const float v = t[tx][ty + i];
        const size_t o = (size_t)(bx + ty + i) * R + by + tx;
        __nv_bfloat16 h = __float2bfloat16(v);
        oh[o] = h;
        ol[o] = __float2bfloat16(v - __bfloat162float(h));
    }
}

// ================================================================
// Scores (fp32 FFMA)
// ================================================================
__global__ void scores_kernel()
{
    __shared__ float Qs[32][128];
    __shared__ float Ks[32][128];

    const int z = blockIdx.z;
    const int b = z >> 4;
    const int h = z & 15;
    const int qbase = b * NC_ + blockIdx.y * 128;
    const int kbase = b * NS_ + blockIdx.x * 128;
    const int hoff = h * 64;
    const int tid = threadIdx.x;
    const int ty = tid >> 4;
    const int tx = tid & 15;

    float acc[8][8];
#pragma unroll
    for (int i = 0; i < 8; i++)
#pragma unroll
        for (int j = 0; j < 8; j++) acc[i][j] = 0.f;

    for (int k0 = 0; k0 < 64; k0 += 32) {
        for (int i = tid; i < 1024; i += 256) {
            const int row = i >> 3;
            const int c4  = (i & 7) << 2;
            float4 q4 = *(const float4*)(g_q + (size_t)(qbase + row) * INNER_ + hoff + k0 + c4);
            Qs[c4 + 0][row] = q4.x; Qs[c4 + 1][row] = q4.y;
            Qs[c4 + 2][row] = q4.z; Qs[c4 + 3][row] = q4.w;
            float4 k4 = *(const float4*)(g_k + (size_t)(kbase + row) * INNER_ + hoff + k0 + c4);
            Ks[c4 + 0][row] = k4.x; Ks[c4 + 1][row] = k4.y;
            Ks[c4 + 2][row] = k4.z; Ks[c4 + 3][row] = k4.w;
        }
        __syncthreads();
#pragma unroll
        for (int kk = 0; kk < 32; kk++) {
            float ar[8], br[8];
#pragma unroll
            for (int i = 0; i < 8; i++) ar[i] = Qs[kk][ty * 8 + i];
#pragma unroll
            for (int j = 0; j < 8; j++) br[j] = Ks[kk][tx * 8 + j];
#pragma unroll
            for (int i = 0; i < 8; i++)
#pragma unroll
                for (int j = 0; j < 8; j++) acc[i][j] = fmaf(ar[i], br[j], acc[i][j]);
        }
        __syncthreads();
    }

    const float scale = 0.125f;
    const size_t zofs = (size_t)z << 22;
#pragma unroll
    for (int i = 0; i < 8; i++) {
        const size_t row = (size_t)(blockIdx.y * 128 + ty * 8 + i);
#pragma unroll
        for (int j4 = 0; j4 < 8; j4 += 4) {
            const int col = blockIdx.x * 128 + tx * 8 + j4;
            float4 r = make_float4(acc[i][j4] * scale, acc[i][j4 + 1] * scale,
                                   acc[i][j4 + 2] * scale, acc[i][j4 + 3] * scale);
            *(float4*)(g_attn + zofs + row * NS_ + col) = r;
        }
    }
}

// ================================================================
// Row softmax over NS=1024, in place.
// ================================================================
__global__ void softmax_kernel()
{
    __shared__ float red[9];
    const size_t row = blockIdx.x;
    float* p = g_attn + row * NS_;
    const int tid = threadIdx.x;

    float4 v = reinterpret_cast<float4*>(p)[tid];
    float m = fmaxf(fmaxf(v.x, v.y), fmaxf(v.z, v.w));
#pragma unroll
    for (int o = 16; o; o >>= 1) m = fmaxf(m, __shfl_xor_sync(0xffffffffu, m, o));
    if ((tid & 31) == 0) red[tid >> 5] = m;
    __syncthreads();
    if (tid == 0) {
        float mm = red[0];
#pragma unroll
        for (int i = 1; i < 8; i++) mm = fmaxf(mm, red[i]);
        red[8] = mm;
    }
    __syncthreads();
    m = red[8];
    __syncthreads();

    v.x = __expf(v.x - m); v.y = __expf(v.y - m);
    v.z = __expf(v.z - m); v.w = __expf(v.w - m);
    float s = v.x + v.y + v.z + v.w;
#pragma unroll
    for (int o = 16; o; o >>= 1) s += __shfl_xor_sync(0xffffffffu, s, o);
    if ((tid & 31) == 0) red[tid >> 5] = s;
    __syncthreads();
    if (tid == 0) {
        float ss = 0.f;
#pragma unroll
        for (int i = 0; i < 8; i++) ss += red[i];
        red[8] = 1.f / ss;
    }
    __syncthreads();
    const float inv = red[8];
    v.x *= inv; v.y *= inv; v.z *= inv; v.w *= inv;
    reinterpret_cast<float4*>(p)[tid] = v;
}

// ================================================================
// attn_mean over heads -> d_out 2nd half
// ================================================================
__global__ void attn_mean_kernel(float* __restrict__ out2)
{
    const size_t idx = (size_t)blockIdx.x * 256 + threadIdx.x;
    const int b = (int)(idx >> 22);
    const size_t r = idx & ((1u << 22) - 1);
    float s = 0.f;
#pragma unroll
    for (int h = 0; h < H_; h++)
        s += g_attn[(((size_t)(b * H_ + h)) << 22) + r];
    out2[idx] = s * (1.0f / 16.0f);
}

// ================================================================
// AV (fp32 FFMA), epilogue emits bf16 hi/lo split for O-proj
// ================================================================
__global__ void av_kernel()
{
    __shared__ float Ps[16][128];
    __shared__ float Vs[16][64];

    const int z = blockIdx.z;
    const int b = z >> 4;
    const int h = z & 15;
    const int by = blockIdx.y;
    const int hoff = h * 64;
    const int tid = threadIdx.x;
    const int ty = tid >> 4;
    const int tx = tid & 15;
    const size_t zofs = (size_t)z << 22;

    float acc[8][4];
#pragma unroll
    for (int i = 0; i < 8; i++)
#pragma unroll
        for (int j = 0; j < 4; j++) acc[i][j] = 0.f;

    for (int k0 = 0; k0 < NS_; k0 += 16) {
        for (int i = tid; i < 512; i += 256) {
            const int row = i >> 2;
            const int c4  = (i & 3) << 2;
            float4 p4 = *(const float4*)(g_attn + zofs + (size_t)(by * 128 + row) * NS_ + k0 + c4);
            Ps[c4 + 0][row] = p4.x; Ps[c4 + 1][row] = p4.y;
            Ps[c4 + 2][row] = p4.z; Ps[c4 + 3][row] = p4.w;
        }
        {
            const int row = tid >> 4;
            const int c4  = (tid & 15) << 2;
            float4 v4 = *(const float4*)(g_v + (size_t)(b * NS_ + k0 + row) * INNER_ + hoff + c4);
            *(float4*)&Vs[row][c4] = v4;
        }
        __syncthreads();

#pragma unroll
        for (int kk = 0; kk < 16; kk++) {
            float ar[8], br[4];
#pragma unroll
            for (int i = 0; i < 8; i++) ar[i] = Ps[kk][ty * 8 + i];
#pragma unroll
            for (int j = 0; j < 4; j++) br[j] = Vs[kk][tx * 4 + j];
#pragma unroll
            for (int i = 0; i < 8; i++)
#pragma unroll
                for (int j = 0; j < 4; j++) acc[i][j] = fmaf(ar[i], br[j], acc[i][j]);
        }
        __syncthreads();
    }

#pragma unroll
    for (int i = 0; i < 8; i++) {
        const size_t row = (size_t)(b * NC_ + by * 128 + ty * 8 + i);
        const size_t idx = row * INNER_ + hoff + tx * 4;
        __align__(8) __nv_bfloat16 hh[4], ll[4];
#pragma unroll
        for (int j = 0; j < 4; j++) {
            hh[j] = __float2bfloat16(acc[i][j]);
            ll[j] = __float2bfloat16(acc[i][j] - __bfloat162float(hh[j]));
        }
        *(uint2*)(g_avh + idx) = *(uint2*)hh;
        *(uint2*)(g_avl + idx) = *(uint2*)ll;
    }
}

// ================================================================
// LayerNorm rows of g_x -> d_out first half
// ================================================================
__global__ void ln_kernel(const float* __restrict__ gamma,
                          const float* __restrict__ beta,
                          float* __restrict__ out)
{
    __shared__ float reds[9];
    __shared__ float redq[9];
    const size_t row = blockIdx.x;
    const int tid = threadIdx.x;

    float4 x = reinterpret_cast<const float4*>(g_x + row * CD_)[tid];
    float s = x.x + x.y + x.z + x.w;
    float q = x.x * x.x + x.y * x.y + x.z * x.z + x.w * x.w;
#pragma unroll
    for (int o = 16; o; o >>= 1) {
        s += __shfl_xor_sync(0xffffffffu, s, o);
        q += __shfl_xor_sync(0xffffffffu, q, o);
    }
    if ((tid & 31) == 0) { reds[tid >> 5] = s; redq[tid >> 5] = q; }
    __syncthreads();
    if (tid == 0) {
        float ss = 0.f, qq = 0.f;
#pragma unroll
        for (int i = 0; i < 8; i++) { ss += reds[i]; qq += redq[i]; }
        reds[8] = ss; redq[8] = qq;
    }
    __syncthreads();
    const float mu = reds[8] * (1.0f / 1024.0f);
    const float var = redq[8] * (1.0f / 1024.0f) - mu * mu;
    const float rstd = rsqrtf(var + LN_EPS);

    float4 g = reinterpret_cast<const float4*>(gamma)[tid];
    float4 bb = reinterpret_cast<const float4*>(beta)[tid];
    float4 r;
    r.x = (x.x - mu) * rstd * g.x + bb.x;
    r.y = (x.y - mu) * rstd * g.y + bb.y;
    r.z = (x.z - mu) * rstd * g.z + bb.z;
    r.w = (x.w - mu) * rstd * g.w + bb.w;
    reinterpret_cast<float4*>(out + row * CD_)[tid] = r;
}

// ================================================================
extern "C" void kernel_launch(void* const* d_in, const int* in_sizes, int n_in,
                              void* d_out, int out_size)
{
    const float* content = (const float*)d_in[0];
    const float* style   = (const float*)d_in[1];
    const float* Wq      = (const float*)d_in[2];
    const float* Wk      = (const float*)d_in[3];
    const float* Wv      = (const float*)d_in[4];
    const float* Wo      = (const float*)d_in[5];
    const float* bo      = (const float*)d_in[6];
    const float* gamma   = (const float*)d_in[7];
    const float* beta    = (const float*)d_in[8];
    float* out = (float*)d_out;
    float* out_attn = out + (size_t)B_ * NC_ * CD_;

    cudaFuncSetAttribute(gemm_mma, cudaFuncAttributeMaxDynamicSharedMemorySize, GSMEM_B);

    // Resolve real device addresses of __device__ symbols (host shadow trap!)
    float *p_q, *p_k, *p_v, *p_x;
    __nv_bfloat16 *p_chi, *p_clo, *p_shi, *p_slo, *p_avh, *p_avl;
    __nv_bfloat16 *p_wqh, *p_wql, *p_wkh, *p_wkl, *p_wvh, *p_wvl, *p_woh, *p_wol;
    cudaGetSymbolAddress((void**)&p_q,   g_q);
    cudaGetSymbolAddress((void**)&p_k,   g_k);
    cudaGetSymbolAddress((void**)&p_v,   g_v);
    cudaGetSymbolAddress((void**)&p_x,   g_x);
    cudaGetSymbolAddress((void**)&p_chi, g_c_hi);
    cudaGetSymbolAddress((void**)&p_clo, g_c_lo);
    cudaGetSymbolAddress((void**)&p_shi, g_s_hi);
    cudaGetSymbolAddress((void**)&p_slo, g_s_lo);
    cudaGetSymbolAddress((void**)&p_avh, g_avh);
    cudaGetSymbolAddress((void**)&p_avl, g_avl);
    cudaGetSymbolAddress((void**)&p_wqh, g_wqt_hi);
    cudaGetSymbolAddress((void**)&p_wql, g_wqt_lo);
    cudaGetSymbolAddress((void**)&p_wkh, g_wkt_hi);
    cudaGetSymbolAddress((void**)&p_wkl, g_wkt_lo);
    cudaGetSymbolAddress((void**)&p_wvh, g_wvt_hi);
    cudaGetSymbolAddress((void**)&p_wvl, g_wvt_lo);
    cudaGetSymbolAddress((void**)&p_woh, g_wot_hi);
    cudaGetSymbolAddress((void**)&p_wol, g_wot_lo);

    // 0) bf16 hi/lo splits of activations + transposed weights
    split_kernel<<<(B_ * NC_ * CD_ / 4 + 255) / 256, 256>>>(
        (const float4*)content, (uint2*)p_chi, (uint2*)p_clo, B_ * NC_ * CD_ / 4);
    split_kernel<<<(B_ * NS_ * SD_ / 4 + 255) / 256, 256>>>(
        (const float4*)style, (uint2*)p_shi, (uint2*)p_slo, B_ * NS_ * SD_ / 4);
    tsplit_kernel<<<dim3(32, 32), dim3(32, 8)>>>(Wq, p_wqh, p_wql, CD_, INNER_);
    tsplit_kernel<<<dim3(32, 24), dim3(32, 8)>>>(Wk, p_wkh, p_wkl, SD_, INNER_);
    tsplit_kernel<<<dim3(32, 24), dim3(32, 8)>>>(Wv, p_wvh, p_wvl, SD_, INNER_);
    tsplit_kernel<<<dim3(32, 32), dim3(32, 8)>>>(Wo, p_woh, p_wol, INNER_, CD_);

    // 1-2) projections via warp MMA (bf16 split)
    gemm_mma<<<dim3(INNER_ / 128, B_ * NC_ / 128), 256, GSMEM_B>>>(
        p_chi, p_clo, p_wqh, p_wql, p_q, B_ * NC_, INNER_, CD_, nullptr, nullptr);
    gemm_mma<<<dim3(INNER_ / 128, B_ * NS_ / 128), 256, GSMEM_B>>>(
        p_shi, p_slo, p_wkh, p_wkl, p_k, B_ * NS_, INNER_, SD_, nullptr, nullptr);
    gemm_mma<<<dim3(INNER_ / 128, B_ * NS_ / 128), 256, GSMEM_B>>>(
        p_shi, p_slo, p_wvh, p_wvl, p_v, B_ * NS_, INNER_, SD_, nullptr, nullptr);

    // 3) scores
    {
        dim3 grid(NS_ / 128, NC_ / 128, B_ * H_);
        scores_kernel<<<grid, 256>>>();
    }
    // 4) softmax in place
    softmax_kernel<<<B_ * H_ * NC_, 256>>>();
    // 5) head-mean -> second output
    attn_mean_kernel<<<(B_ * NC_ * NS_) / 256, 256>>>(out_attn);
    // 6) av = attn @ V  (emits bf16 hi/lo)
    {
        dim3 grid(1, NC_ / 128, B_ * H_);
        av_kernel<<<grid, 256>>>();
    }
    // 7) x = av @ Wo + bo + content  (warp MMA)
    gemm_mma<<<dim3(CD_ / 128, B_ * NC_ / 128), 256, GSMEM_B>>>(
        p_avh, p_avl, p_woh, p_wol, p_x, B_ * NC_, CD_, INNER_, bo, content);
    // 8) LayerNorm -> first output
    ln_kernel<<<B_ * NC_, 256>>>(gamma, beta, out);
}

// round 5
// speedup vs baseline: 2.1776x; 1.5710x over previous
#include <cuda_runtime.h>
#include <cuda_bf16.h>
#include <math.h>
#include <stdint.h>

#define B_    4
#define NC_   4096
#define NS_   1024
#define CD_   1024
#define SD_   768
#define H_    16
#define D_    64
#define INNER_ 1024
#define LN_EPS 1e-5f

// ---------------- static device scratch ----------------
__device__ float g_attn[(size_t)B_ * H_ * NC_ * NS_];   // 1 GB: scores fp32, then probs hi/lo bf16 in place
__device__ float g_x[(size_t)B_ * NC_ * CD_];           // pre-LN residual
__device__ float g_v[(size_t)B_ * NS_ * INNER_];        // V projection fp32

__device__ __nv_bfloat16 g_c_hi[(size_t)B_ * NC_ * CD_];
__device__ __nv_bfloat16 g_c_lo[(size_t)B_ * NC_ * CD_];
__device__ __nv_bfloat16 g_s_hi[(size_t)B_ * NS_ * SD_];
__device__ __nv_bfloat16 g_s_lo[(size_t)B_ * NS_ * SD_];
__device__ __nv_bfloat16 g_qh[(size_t)B_ * NC_ * INNER_];   // Q (pre-scaled) hi/lo
__device__ __nv_bfloat16 g_ql[(size_t)B_ * NC_ * INNER_];
__device__ __nv_bfloat16 g_kh[(size_t)B_ * NS_ * INNER_];
__device__ __nv_bfloat16 g_kl[(size_t)B_ * NS_ * INNER_];
__device__ __nv_bfloat16 g_vth[(size_t)B_ * INNER_ * NS_];  // V^T per head [z*64+d][s]
__device__ __nv_bfloat16 g_vtl[(size_t)B_ * INNER_ * NS_];
__device__ __nv_bfloat16 g_avh[(size_t)B_ * NC_ * INNER_];
__device__ __nv_bfloat16 g_avl[(size_t)B_ * NC_ * INNER_];

__device__ __nv_bfloat16 g_wqt_hi[INNER_ * CD_];
__device__ __nv_bfloat16 g_wqt_lo[INNER_ * CD_];
__device__ __nv_bfloat16 g_wkt_hi[INNER_ * SD_];
__device__ __nv_bfloat16 g_wkt_lo[INNER_ * SD_];
__device__ __nv_bfloat16 g_wvt_hi[INNER_ * SD_];
__device__ __nv_bfloat16 g_wvt_lo[INNER_ * SD_];
__device__ __nv_bfloat16 g_wot_hi[CD_ * INNER_];
__device__ __nv_bfloat16 g_wot_lo[CD_ * INNER_];

// ================= helpers =================
__device__ __forceinline__ uint32_t smem_u32(const void* p) {
    uint32_t a;
    asm("{ .reg .u64 t; cvta.to.shared.u64 t, %1; cvt.u32.u64 %0, t; }" : "=r"(a) : "l"(p));
    return a;
}
__device__ __forceinline__ void ldsm_x4(uint32_t* f, uint32_t addr) {
    asm volatile("ldmatrix.sync.aligned.m8n8.x4.shared.b16 {%0,%1,%2,%3}, [%4];"
                 : "=r"(f[0]), "=r"(f[1]), "=r"(f[2]), "=r"(f[3]) : "r"(addr));
}
__device__ __forceinline__ void ldsm_x2(uint32_t* f, uint32_t addr) {
    asm volatile("ldmatrix.sync.aligned.m8n8.x2.shared.b16 {%0,%1}, [%2];"
                 : "=r"(f[0]), "=r"(f[1]) : "r"(addr));
}
__device__ __forceinline__ void mma_bf16(float* c, const uint32_t* a, const uint32_t* b) {
    asm volatile("mma.sync.aligned.m16n8k16.row.col.f32.bf16.bf16.f32 "
                 "{%0,%1,%2,%3}, {%4,%5,%6,%7}, {%8,%9}, {%0,%1,%2,%3};"
                 : "+f"(c[0]), "+f"(c[1]), "+f"(c[2]), "+f"(c[3])
                 : "r"(a[0]), "r"(a[1]), "r"(a[2]), "r"(a[3]), "r"(b[0]), "r"(b[1]));
}
__device__ __forceinline__ uint32_t pack_hi2(float a, float b) {
    __nv_bfloat162 t = __floats2bfloat162_rn(a, b);
    return *(uint32_t*)&t;
}

// ================================================================
// Generic bf16-split GEMM: C = (Ah+Al)[M,K] @ (Bh+Bl)[N,K]^T
// 128x128 tile, BK=32, 256 thr = 8 warps (2Mx4N, 64x32 each), dbuf smem.
// Output: fp32 C (+bias+resid) OR bf16 hi/lo (Oh/Ol) with alpha.
// ================================================================
#define TILE_B   10240
#define BUF_B    (4 * TILE_B)
#define GSMEM_B  (2 * BUF_B)

__global__ void __launch_bounds__(256, 1) gemm_mma(
    const __nv_bfloat16* __restrict__ Ah, const __nv_bfloat16* __restrict__ Al,
    const __nv_bfloat16* __restrict__ Bh, const __nv_bfloat16* __restrict__ Bl,
    float* __restrict__ C, __nv_bfloat16* __restrict__ Oh, __nv_bfloat16* __restrict__ Ol,
    int M, int N, int K,
    const float* __restrict__ bias, const float* __restrict__ resid, float alpha)
{
    extern __shared__ char sm[];
    const int tid = threadIdx.x;
    const int lane = tid & 31;
    const int wid = tid >> 5;
    const int bm = blockIdx.y * 128;
    const int bn = blockIdx.x * 128;
    const int nch = K >> 5;

    const int wm = (wid >> 2) * 64;
    const int wn = (wid & 3) * 32;

    const uint32_t sA = smem_u32(sm);
    const uint32_t a_off = (uint32_t)(lane & 15) * 80 + (uint32_t)(lane >> 4) * 16;
    const uint32_t b_off = (uint32_t)(lane & 7) * 80 + (uint32_t)((lane >> 3) & 1) * 16;

    float acc[4][4][4];
#pragma unroll
    for (int mt = 0; mt < 4; mt++)
#pragma unroll
        for (int nt = 0; nt < 4; nt++)
#pragma unroll
            for (int r = 0; r < 4; r++) acc[mt][nt][r] = 0.f;

#pragma unroll
    for (int it = 0; it < 8; it++) {
        const int idx = (it << 8) + tid;
        const int t = idx >> 9;
        const int r = (idx >> 2) & 127;
        const int s = idx & 3;
        const __nv_bfloat16* src = (t == 0) ? Ah : (t == 1) ? Al : (t == 2) ? Bh : Bl;
        const int rb = (t < 2) ? bm : bn;
        uint4 v = *(const uint4*)(src + (size_t)(rb + r) * K + s * 8);
        *(uint4*)(sm + t * TILE_B + r * 80 + s * 16) = v;
    }
    __syncthreads();

    for (int c = 0; c < nch; c++) {
        uint4 g[8];
        if (c + 1 < nch) {
            const int ko = (c + 1) << 5;
#pragma unroll
            for (int it = 0; it < 8; it++) {
                const int idx = (it << 8) + tid;
                const int t = idx >> 9;
                const int r = (idx >> 2) & 127;
                const int s = idx & 3;
                const __nv_bfloat16* src = (t == 0) ? Ah : (t == 1) ? Al : (t == 2) ? Bh : Bl;
                const int rb = (t < 2) ? bm : bn;
                g[it] = *(const uint4*)(src + (size_t)(rb + r) * K + ko + s * 8);
            }
        }
        {
            const uint32_t base = sA + (uint32_t)(c & 1) * BUF_B;
#pragma unroll
            for (int kk = 0; kk < 2; kk++) {
                const uint32_t ko = kk * 32;
                uint32_t bh[4][2], bl[4][2];
#pragma unroll
                for (int nt = 0; nt < 4; nt++) {
                    ldsm_x2(bh[nt], base + 2 * TILE_B + (uint32_t)(wn + nt * 8) * 80 + b_off + ko);
                    ldsm_x2(bl[nt], base + 3 * TILE_B + (uint32_t)(wn + nt * 8) * 80 + b_off + ko);
                }
#pragma unroll
                for (int mt = 0; mt < 4; mt++) {
                    uint32_t ah[4], al[4];
                    ldsm_x4(ah, base + (uint32_t)(wm + mt * 16) * 80 + a_off + ko);
                    ldsm_x4(al, base + TILE_B + (uint32_t)(wm + mt * 16) * 80 + a_off + ko);
#pragma unroll
                    for (int nt = 0; nt < 4; nt++) {
                        mma_bf16(acc[mt][nt], ah, bh[nt]);
                        mma_bf16(acc[mt][nt], ah, bl[nt]);
                        mma_bf16(acc[mt][nt], al, bh[nt]);
                    }
                }
            }
        }
        if (c + 1 < nch) {
            char* dst = sm + ((c + 1) & 1) * BUF_B;
#pragma unroll
            for (int it = 0; it < 8; it++) {
                const int idx = (it << 8) + tid;
                const int t = idx >> 9;
                const int r = (idx >> 2) & 127;
                const int s = idx & 3;
                *(uint4*)(dst + t * TILE_B + r * 80 + s * 16) = g[it];
            }
        }
        __syncthreads();
    }

#pragma unroll
    for (int mt = 0; mt < 4; mt++) {
        const int row0 = bm + wm + mt * 16 + (lane >> 2);
#pragma unroll
        for (int nt = 0; nt < 4; nt++) {
            const int col = bn + wn + nt * 8 + (lane & 3) * 2;
#pragma unroll
            for (int half = 0; half < 2; half++) {
                const int row = row0 + half * 8;
                float vx = acc[mt][nt][half * 2] * alpha;
                float vy = acc[mt][nt][half * 2 + 1] * alpha;
                if (Oh) {
                    __nv_bfloat16 hx = __float2bfloat16(vx);
                    __nv_bfloat16 hy = __float2bfloat16(vy);
                    uint32_t hp = ((uint32_t)*(uint16_t*)&hy << 16) | *(uint16_t*)&hx;
                    __nv_bfloat16 lx = __float2bfloat16(vx - __bfloat162float(hx));
                    __nv_bfloat16 ly = __float2bfloat16(vy - __bfloat162float(hy));
                    uint32_t lp = ((uint32_t)*(uint16_t*)&ly << 16) | *(uint16_t*)&lx;
                    *(uint32_t*)(Oh + (size_t)row * N + col) = hp;
                    *(uint32_t*)(Ol + (size_t)row * N + col) = lp;
                } else {
                    if (bias) { vx += bias[col]; vy += bias[col + 1]; }
                    if (resid) {
                        float2 t = *(const float2*)(resid + (size_t)row * N + col);
                        vx += t.x; vy += t.y;
                    }
                    *(float2*)(C + (size_t)row * N + col) = make_float2(vx, vy);
                }
            }
        }
    }
}

// ================================================================
// scores_mma: S[z][q][k] = sum_d Qs[q][h*64+d] * Ks[k][h*64+d]
// (Q pre-scaled by 1/8). 128x128 tile, K=64 fully resident, no pipeline.
// grid (NS/128, NC/128, 64), 256 thr. smem 4*18432 = 73728.
// ================================================================
#define STILE_B 18432  // 128 rows * 144 B

__global__ void __launch_bounds__(256, 1) scores_mma()
{
    extern __shared__ char sm[];
    const int tid = threadIdx.x;
    const int lane = tid & 31;
    const int wid = tid >> 5;
    const int z = blockIdx.z;
    const int b = z >> 4;
    const int h = z & 15;
    const int q0 = b * NC_ + blockIdx.y * 128;
    const int k0 = b * NS_ + blockIdx.x * 128;

    const int wm = (wid >> 2) * 64;
    const int wn = (wid & 3) * 32;
    const uint32_t sA = smem_u32(sm);
    const uint32_t a_off = (uint32_t)(lane & 15) * 144 + (uint32_t)(lane >> 4) * 16;
    const uint32_t b_off = (uint32_t)(lane & 7) * 144 + (uint32_t)((lane >> 3) & 1) * 16;

    float acc[4][4][4];
#pragma unroll
    for (int mt = 0; mt < 4; mt++)
#pragma unroll
        for (int nt = 0; nt < 4; nt++)
#pragma unroll
            for (int r = 0; r < 4; r++) acc[mt][nt][r] = 0.f;

#pragma unroll
    for (int it = 0; it < 16; it++) {
        const int idx = (it << 8) + tid;
        const int t = idx >> 10;            // 0 Qh, 1 Ql, 2 Kh, 3 Kl
        const int r = (idx >> 3) & 127;
        const int s = idx & 7;
        const __nv_bfloat16* src = (t == 0) ? g_qh : (t == 1) ? g_ql : (t == 2) ? g_kh : g_kl;
        const int rb = (t < 2) ? q0 : k0;
        uint4 v = *(const uint4*)(src + (size_t)(rb + r) * INNER_ + h * 64 + s * 8);
        *(uint4*)(sm + t * STILE_B + r * 144 + s * 16) = v;
    }
    __syncthreads();

#pragma unroll
    for (int kk = 0; kk < 4; kk++) {
        const uint32_t ko = kk * 32;
        uint32_t bh[4][2], bl[4][2];
#pragma unroll
        for (int nt = 0; nt < 4; nt++) {
            ldsm_x2(bh[nt], sA + 2 * STILE_B + (uint32_t)(wn + nt * 8) * 144 + b_off + ko);
            ldsm_x2(bl[nt], sA + 3 * STILE_B + (uint32_t)(wn + nt * 8) * 144 + b_off + ko);
        }
#pragma unroll
        for (int mt = 0; mt < 4; mt++) {
            uint32_t ah[4], al[4];
            ldsm_x4(ah, sA + (uint32_t)(wm + mt * 16) * 144 + a_off + ko);
            ldsm_x4(al, sA + STILE_B + (uint32_t)(wm + mt * 16) * 144 + a_off + ko);
#pragma unroll
            for (int nt = 0; nt < 4; nt++) {
                mma_bf16(acc[mt][nt], ah, bh[nt]);
                mma_bf16(acc[mt][nt], ah, bl[nt]);
                mma_bf16(acc[mt][nt], al, bh[nt]);
            }
        }
    }

    float* Cz = g_attn + ((size_t)z << 22);
#pragma unroll
    for (int mt = 0; mt < 4; mt++) {
        const int row0 = blockIdx.y * 128 + wm + mt * 16 + (lane >> 2);
#pragma unroll
        for (int nt = 0; nt < 4; nt++) {
            const int col = blockIdx.x * 128 + wn + nt * 8 + (lane & 3) * 2;
#pragma unroll
            for (int half = 0; half < 2; half++) {
                *(float2*)(Cz + (size_t)(row0 + half * 8) * NS_ + col) =
                    make_float2(acc[mt][nt][half * 2], acc[mt][nt][half * 2 + 1]);
            }
        }
    }
}

// ================================================================
// softmax: fp32 scores row -> probs, written as bf16 hi(1024)+lo(1024)
// IN PLACE in the same 4 KB row. grid = B*H*NC, 256 thr.
// ================================================================
__global__ void softmax_kernel()
{
    __shared__ float red[9];
    const size_t row = blockIdx.x;
    float* p = g_attn + row * NS_;
    const int tid = threadIdx.x;

    float4 v = reinterpret_cast<float4*>(p)[tid];
    float m = fmaxf(fmaxf(v.x, v.y), fmaxf(v.z, v.w));
#pragma unroll
    for (int o = 16; o; o >>= 1) m = fmaxf(m, __shfl_xor_sync(0xffffffffu, m, o));
    if ((tid & 31) == 0) red[tid >> 5] = m;
    __syncthreads();
    if (tid == 0) {
        float mm = red[0];
#pragma unroll
        for (int i = 1; i < 8; i++) mm = fmaxf(mm, red[i]);
        red[8] = mm;
    }
    __syncthreads();
    m = red[8];

    v.x = __expf(v.x - m); v.y = __expf(v.y - m);
    v.z = __expf(v.z - m); v.w = __expf(v.w - m);
    float s = v.x + v.y + v.z + v.w;
#pragma unroll
    for (int o = 16; o; o >>= 1) s += __shfl_xor_sync(0xffffffffu, s, o);
    if ((tid & 31) == 0) red[tid >> 5] = s;
    __syncthreads();
    if (tid == 0) {
        float ss = 0.f;
#pragma unroll
        for (int i = 0; i < 8; i++) ss += red[i];
        red[8] = 1.f / ss;
    }
    __syncthreads();   // also orders all row reads before the in-place writes
    const float inv = red[8];
    v.x *= inv; v.y *= inv; v.z *= inv; v.w *= inv;

    uint32_t hp[2], lp[2];
    {
        __nv_bfloat16 hx = __float2bfloat16(v.x), hy = __float2bfloat16(v.y);
        __nv_bfloat16 hz = __float2bfloat16(v.z), hw = __float2bfloat16(v.w);
        hp[0] = ((uint32_t)*(uint16_t*)&hy << 16) | *(uint16_t*)&hx;
        hp[1] = ((uint32_t)*(uint16_t*)&hw << 16) | *(uint16_t*)&hz;
        __nv_bfloat16 lx = __float2bfloat16(v.x - __bfloat162float(hx));
        __nv_bfloat16 ly = __float2bfloat16(v.y - __bfloat162float(hy));
        __nv_bfloat16 lz = __float2bfloat16(v.z - __bfloat162float(hz));
        __nv_bfloat16 lw = __float2bfloat16(v.w - __bfloat162float(hw));
        lp[0] = ((uint32_t)*(uint16_t*)&ly << 16) | *(uint16_t*)&lx;
        lp[1] = ((uint32_t)*(uint16_t*)&lw << 16) | *(uint16_t*)&lz;
    }
    uint2* hout = (uint2*)p;                       // bytes [0, 2048)
    uint2* lout = (uint2*)((char*)p + 2048);       // bytes [2048, 4096)
    hout[tid] = make_uint2(hp[0], hp[1]);
    lout[tid] = make_uint2(lp[0], lp[1]);
}

// ================================================================
// attn_mean from hi/lo bf16 probs -> d_out 2nd half
// each thread: 4 consecutive k of one (b,q) row.
// ================================================================
__global__ void attn_mean_kernel(float* __restrict__ out2)
{
    const size_t idx = (size_t)blockIdx.x * 256 + threadIdx.x;   // < B*NC*NS/4
    const size_t e0 = idx << 2;
    const int b = (int)(e0 >> 22);
    const int q = (int)((e0 >> 10) & 4095);
    const int k = (int)(e0 & 1023);
    const __nv_bfloat16* pb = (const __nv_bfloat16*)g_attn;

    float s0 = 0.f, s1 = 0.f, s2 = 0.f, s3 = 0.f;
#pragma unroll
    for (int h = 0; h < H_; h++) {
        const size_t row = ((size_t)(b * H_ + h) << 12) + q;
        const __nv_bfloat16* ph = pb + row * 2048 + k;
        uint2 hv = *(const uint2*)ph;
        uint2 lv = *(const uint2*)(ph + 1024);
        float2 h0 = __bfloat1622float2(*(__nv_bfloat162*)&hv.x);
        float2 h1 = __bfloat1622float2(*(__nv_bfloat162*)&hv.y);
        float2 l0 = __bfloat1622float2(*(__nv_bfloat162*)&lv.x);
        float2 l1 = __bfloat1622float2(*(__nv_bfloat162*)&lv.y);
        s0 += h0.x + l0.x; s1 += h0.y + l0.y;
        s2 += h1.x + l1.x; s3 += h1.y + l1.y;
    }
    const float c = 1.0f / 16.0f;
    *(float4*)(out2 + e0) = make_float4(s0 * c, s1 * c, s2 * c, s3 * c);
}

// ================================================================
// av_mma: av[q][h*64+d] = sum_k P[z][q][k] * Vt[z*64+d][k]
// 128x64 tile (MxN), K=1024 in 64-chunks, double buffered.
// 8 warps = 2M x 4N, warp tile 64x16. grid (NC/128, 64).
// smem: buf = Ah,Al(128x144) + Bh,Bl(64x144) = 55296; x2 = 110592.
// ================================================================
#define AV_AT   18432          // 128*144
#define AV_BT   9216           // 64*144
#define AV_BUF  (2 * AV_AT + 2 * AV_BT)   // 55296
#define AV_SMEM (2 * AV_BUF)              // 110592

__global__ void __launch_bounds__(256, 1) av_mma()
{
    extern __shared__ char sm[];
    const int tid = threadIdx.x;
    const int lane = tid & 31;
    const int wid = tid >> 5;
    const int by = blockIdx.x;
    const int z = blockIdx.y;
    const int b = z >> 4;
    const int h = z & 15;

    const int wm = (wid >> 2) * 64;
    const int wn = (wid & 3) * 16;
    const uint32_t sA = smem_u32(sm);
    const uint32_t a_off = (uint32_t)(lane & 15) * 144 + (uint32_t)(lane >> 4) * 16;
    const uint32_t b_off = (uint32_t)(lane & 7) * 144 + (uint32_t)((lane >> 3) & 1) * 16;

    const char* attn_bytes = (const char*)g_attn + (((size_t)z << 12) + (size_t)by * 128 << 12);
    // = g_attn bytes + (z*4096 + by*128) * 4096
    const __nv_bfloat16* vth = g_vth + (size_t)z * 64 * NS_;
    const __nv_bfloat16* vtl = g_vtl + (size_t)z * 64 * NS_;

    float acc[4][2][4];
#pragma unroll
    for (int mt = 0; mt < 4; mt++)
#pragma unroll
        for (int nt = 0; nt < 2; nt++)
#pragma unroll
            for (int r = 0; r < 4; r++) acc[mt][nt][r] = 0.f;

    // loader lambda-ish via macro-expanded loop: 3072 uint4 items / 256 thr = 12
#define AV_LOAD_G(c_, gArr_)                                                          \
    {                                                                                 \
        const int cc = (c_);                                                          \
        _Pragma("unroll")                                                             \
        for (int it = 0; it < 12; it++) {                                             \
            const int item = (it << 8) + tid;                                         \
            if (item < 2048) {                                                        \
                const int half = item >> 10;                                          \
                const int r = (item >> 3) & 127;                                      \
                const int s = item & 7;                                               \
                gArr_[it] = *(const uint4*)(attn_bytes + ((size_t)r << 12)            \
                              + half * 2048 + cc * 128 + s * 16);                     \
            } else {                                                                  \
                const int i2 = item - 2048;                                           \
                const int half = i2 >> 9;                                             \
                const int r = (i2 >> 3) & 63;                                         \
                const int s = i2 & 7;                                                 \
                const __nv_bfloat16* src = half ? vtl : vth;                          \
                gArr_[it] = *(const uint4*)(src + (size_t)r * NS_ + cc * 64 + s * 8); \
            }                                                                         \
        }                                                                             \
    }
#define AV_STORE_S(buf_, gArr_)                                                       \
    {                                                                                 \
        char* dst = sm + (buf_) * AV_BUF;                                             \
        _Pragma("unroll")                                                             \
        for (int it = 0; it < 12; it++) {                                             \
            const int item = (it << 8) + tid;                                         \
            if (item < 2048) {                                                        \
                const int half = item >> 10;                                          \
                const int r = (item >> 3) & 127;                                      \
                const int s = item & 7;                                               \
                *(uint4*)(dst + half * AV_AT + r * 144 + s * 16) = gArr_[it];         \
            } else {                                                                  \
                const int i2 = item - 2048;                                           \
                const int half = i2 >> 9;                                             \
                const int r = (i2 >> 3) & 63;                                         \
                const int s = i2 & 7;                                                 \
                *(uint4*)(dst + 2 * AV_AT + half * AV_BT + r * 144 + s * 16) = gArr_[it]; \
            }                                                                         \
        }                                                                             \
    }

    {
        uint4 g[12];
        AV_LOAD_G(0, g);
        AV_STORE_S(0, g);
    }
    __syncthreads();

    for (int c = 0; c < 16; c++) {
        uint4 g[12];
        if (c + 1 < 16) AV_LOAD_G(c + 1, g);

        {
            const uint32_t base = sA + (uint32_t)(c & 1) * AV_BUF;
#pragma unroll
            for (int kk = 0; kk < 4; kk++) {
                const uint32_t ko = kk * 32;
                uint32_t bh[2][2], bl[2][2];
#pragma unroll
                for (int nt = 0; nt < 2; nt++) {
                    ldsm_x2(bh[nt], base + 2 * AV_AT + (uint32_t)(wn + nt * 8) * 144 + b_off + ko);
                    ldsm_x2(bl[nt], base + 2 * AV_AT + AV_BT + (uint32_t)(wn + nt * 8) * 144 + b_off + ko);
                }
#pragma unroll
                for (int mt = 0; mt < 4; mt++) {
                    uint32_t ah[4], al[4];
                    ldsm_x4(ah, base + (uint32_t)(wm + mt * 16) * 144 + a_off + ko);
                    ldsm_x4(al, base + AV_AT + (uint32_t)(wm + mt * 16) * 144 + a_off + ko);
#pragma unroll
                    for (int nt = 0; nt < 2; nt++) {
                        mma_bf16(acc[mt][nt], ah, bh[nt]);
                        mma_bf16(acc[mt][nt], ah, bl[nt]);
                        mma_bf16(acc[mt][nt], al, bh[nt]);
                    }
                }
            }
        }
        if (c + 1 < 16) AV_STORE_S((c + 1) & 1, g);
        __syncthreads();
    }

    // epilogue -> g_avh/g_avl at [b*NC + q][h*64 + d]
#pragma unroll
    for (int mt = 0; mt < 4; mt++) {
        const int row0 = b * NC_ + by * 128 + wm + mt * 16 + (lane >> 2);
#pragma unroll
        for (int nt = 0; nt < 2; nt++) {
            const int col = h * 64 + wn + nt * 8 + (lane & 3) * 2;
#pragma unroll
            for (int half = 0; half < 2; half++) {
                const int row = row0 + half * 8;
                float vx = acc[mt][nt][half * 2];
                float vy = acc[mt][nt][half * 2 + 1];
                __nv_bfloat16 hx = __float2bfloat16(vx), hy = __float2bfloat16(vy);
                uint32_t hp = ((uint32_t)*(uint16_t*)&hy << 16) | *(uint16_t*)&hx;
                __nv_bfloat16 lx = __float2bfloat16(vx - __bfloat162float(hx));
                __nv_bfloat16 ly = __float2bfloat16(vy - __bfloat162float(hy));
                uint32_t lp = ((uint32_t)*(uint16_t*)&ly << 16) | *(uint16_t*)&lx;
                *(uint32_t*)(g_avh + (size_t)row * INNER_ + col) = hp;
                *(uint32_t*)(g_avl + (size_t)row * INNER_ + col) = lp;
            }
        }
    }
}

// ================================================================
// fp32 -> bf16 hi/lo split
// ================================================================
__global__ void split_kernel(const float4* __restrict__ in,
                             uint2* __restrict__ oh, uint2* __restrict__ ol, int n4)
{
    const int i = blockIdx.x * 256 + threadIdx.x;
    if (i >= n4) return;
    float4 v = in[i];
    __align__(8) __nv_bfloat16 h[4], l[4];
    const float f[4] = {v.x, v.y, v.z, v.w};
#pragma unroll
    for (int j = 0; j < 4; j++) {
        h[j] = __float2bfloat16(f[j]);
        l[j] = __float2bfloat16(f[j] - __bfloat162float(h[j]));
    }
    oh[i] = *(uint2*)h;
    ol[i] = *(uint2*)l;
}

// ================================================================
// Transpose + split weights: fp32 [R][Ncol] -> bf16 [Ncol][R] hi/lo
// ================================================================
__global__ void tsplit_kernel(const float* __restrict__ in,
                              __nv_bfloat16* __restrict__ oh,
                              __nv_bfloat16* __restrict__ ol, int R, int Ncol)
{
    __shared__ float t[32][33];
    const int bx = blockIdx.x * 32, by = blockIdx.y * 32;
    const int tx = threadIdx.x, ty = threadIdx.y;
#pragma unroll
    for (int i = 0; i < 32; i += 8)
        t[ty + i][tx] = in[(size_t)(by + ty + i) * Ncol + bx + tx];
    __syncthreads();
#pragma unroll
    for (int i = 0; i < 32; i += 8) {
        const float v = t[tx][ty + i];
        const size_t o = (size_t)(bx + ty + i) * R + by + tx;
        __nv_bfloat16 h = __float2bfloat16(v);
        oh[o] = h;
        ol[o] = __float2bfloat16(v - __bfloat162float(h));
    }
}

// ================================================================
// V^T split: g_v [b*NS+s][col] -> g_vth/g_vtl [b*1024+col][s]
// grid (1024/32, NS/32, B), block (32,8)
// ================================================================
__global__ void vtsplit_kernel()
{
    __shared__ float t[32][33];
    const int b = blockIdx.z;
    const int bx = blockIdx.x * 32;   // col
    const int by = blockIdx.y * 32;   // s
    const int tx = threadIdx.x, ty = threadIdx.y;
    const float* in = g_v + (size_t)b * NS_ * INNER_;
#pragma unroll
    for (int i = 0; i < 32; i += 8)
        t[ty + i][tx] = in[(size_t)(by + ty + i) * INNER_ + bx + tx];
    __syncthreads();
#pragma unroll
    for (int i = 0; i < 32; i += 8) {
        const float v = t[tx][ty + i];
        const size_t o = (size_t)(b * 1024 + bx + ty + i) * NS_ + by + tx;
        __nv_bfloat16 h = __float2bfloat16(v);
        g_vth[o] = h;
        g_vtl[o] = __float2bfloat16(v - __bfloat162float(h));
    }
}

// ================================================================
// LayerNorm rows of g_x -> d_out first half
// ================================================================
__global__ void ln_kernel(const float* __restrict__ gamma,
                          const float* __restrict__ beta,
                          float* __restrict__ out)
{
    __shared__ float reds[9];
    __shared__ float redq[9];
    const size_t row = blockIdx.x;
    const int tid = threadIdx.x;

    float4 x = reinterpret_cast<const float4*>(g_x + row * CD_)[tid];
    float s = x.x + x.y + x.z + x.w;
    float q = x.x * x.x + x.y * x.y + x.z * x.z + x.w * x.w;
#pragma unroll
    for (int o = 16; o; o >>= 1) {
        s += __shfl_xor_sync(0xffffffffu, s, o);
        q += __shfl_xor_sync(0xffffffffu, q, o);
    }
    if ((tid & 31) == 0) { reds[tid >> 5] = s; redq[tid >> 5] = q; }
    __syncthreads();
    if (tid == 0) {
        float ss = 0.f, qq = 0.f;
#pragma unroll
        for (int i = 0; i < 8; i++) { ss += reds[i]; qq += redq[i]; }
        reds[8] = ss; redq[8] = qq;
    }
    __syncthreads();
    const float mu = reds[8] * (1.0f / 1024.0f);
    const float var = redq[8] * (1.0f / 1024.0f) - mu * mu;
    const float rstd = rsqrtf(var + LN_EPS);

    float4 g = reinterpret_cast<const float4*>(gamma)[tid];
    float4 bb = reinterpret_cast<const float4*>(beta)[tid];
    float4 r;
    r.x = (x.x - mu) * rstd * g.x + bb.x;
    r.y = (x.y - mu) * rstd * g.y + bb.y;
    r.z = (x.z - mu) * rstd * g.z + bb.z;
    r.w = (x.w - mu) * rstd * g.w + bb.w;
    reinterpret_cast<float4*>(out + row * CD_)[tid] = r;
}

// ================================================================
extern "C" void kernel_launch(void* const* d_in, const int* in_sizes, int n_in,
                              void* d_out, int out_size)
{
    const float* content = (const float*)d_in[0];
    const float* style   = (const float*)d_in[1];
    const float* Wq      = (const float*)d_in[2];
    const float* Wk      = (const float*)d_in[3];
    const float* Wv      = (const float*)d_in[4];
    const float* Wo      = (const float*)d_in[5];
    const float* bo      = (const float*)d_in[6];
    const float* gamma   = (const float*)d_in[7];
    const float* beta    = (const float*)d_in[8];
    float* out = (float*)d_out;
    float* out_attn = out + (size_t)B_ * NC_ * CD_;

    cudaFuncSetAttribute(gemm_mma,   cudaFuncAttributeMaxDynamicSharedMemorySize, GSMEM_B);
    cudaFuncSetAttribute(scores_mma, cudaFuncAttributeMaxDynamicSharedMemorySize, 4 * STILE_B);
    cudaFuncSetAttribute(av_mma,     cudaFuncAttributeMaxDynamicSharedMemorySize, AV_SMEM);

    float *p_v, *p_x;
    __nv_bfloat16 *p_chi, *p_clo, *p_shi, *p_slo, *p_avh, *p_avl;
    __nv_bfloat16 *p_qh, *p_ql, *p_kh, *p_kl;
    __nv_bfloat16 *p_wqh, *p_wql, *p_wkh, *p_wkl, *p_wvh, *p_wvl, *p_woh, *p_wol;
    cudaGetSymbolAddress((void**)&p_v,   g_v);
    cudaGetSymbolAddress((void**)&p_x,   g_x);
    cudaGetSymbolAddress((void**)&p_chi, g_c_hi);
    cudaGetSymbolAddress((void**)&p_clo, g_c_lo);
    cudaGetSymbolAddress((void**)&p_shi, g_s_hi);
    cudaGetSymbolAddress((void**)&p_slo, g_s_lo);
    cudaGetSymbolAddress((void**)&p_qh,  g_qh);
    cudaGetSymbolAddress((void**)&p_ql,  g_ql);
    cudaGetSymbolAddress((void**)&p_kh,  g_kh);
    cudaGetSymbolAddress((void**)&p_kl,  g_kl);
    cudaGetSymbolAddress((void**)&p_avh, g_avh);
    cudaGetSymbolAddress((void**)&p_avl, g_avl);
    cudaGetSymbolAddress((void**)&p_wqh, g_wqt_hi);
    cudaGetSymbolAddress((void**)&p_wql, g_wqt_lo);
    cudaGetSymbolAddress((void**)&p_wkh, g_wkt_hi);
    cudaGetSymbolAddress((void**)&p_wkl, g_wkt_lo);
    cudaGetSymbolAddress((void**)&p_wvh, g_wvt_hi);
    cudaGetSymbolAddress((void**)&p_wvl, g_wvt_lo);
    cudaGetSymbolAddress((void**)&p_woh, g_wot_hi);
    cudaGetSymbolAddress((void**)&p_wol, g_wot_lo);

    // 0) splits
    split_kernel<<<(B_ * NC_ * CD_ / 4 + 255) / 256, 256>>>(
        (const float4*)content, (uint2*)p_chi, (uint2*)p_clo, B_ * NC_ * CD_ / 4);
    split_kernel<<<(B_ * NS_ * SD_ / 4 + 255) / 256, 256>>>(
        (const float4*)style, (uint2*)p_shi, (uint2*)p_slo, B_ * NS_ * SD_ / 4);
    tsplit_kernel<<<dim3(32, 32), dim3(32, 8)>>>(Wq, p_wqh, p_wql, CD_, INNER_);
    tsplit_kernel<<<dim3(32, 24), dim3(32, 8)>>>(Wk, p_wkh, p_wkl, SD_, INNER_);
    tsplit_kernel<<<dim3(32, 24), dim3(32, 8)>>>(Wv, p_wvh, p_wvl, SD_, INNER_);
    tsplit_kernel<<<dim3(32, 32), dim3(32, 8)>>>(Wo, p_woh, p_wol, INNER_, CD_);

    // 1) Q proj -> bf16 hi/lo, pre-scaled by 1/8
    gemm_mma<<<dim3(INNER_ / 128, B_ * NC_ / 128), 256, GSMEM_B>>>(
        p_chi, p_clo, p_wqh, p_wql, nullptr, p_qh, p_ql,
        B_ * NC_, INNER_, CD_, nullptr, nullptr, 0.125f);
    // 2) K proj -> bf16 hi/lo
    gemm_mma<<<dim3(INNER_ / 128, B_ * NS_ / 128), 256, GSMEM_B>>>(
        p_shi, p_slo, p_wkh, p_wkl, nullptr, p_kh, p_kl,
        B_ * NS_, INNER_, SD_, nullptr, nullptr, 1.0f);
    // 3) V proj -> fp32, then per-head transpose+split
    gemm_mma<<<dim3(INNER_ / 128, B_ * NS_ / 128), 256, GSMEM_B>>>(
        p_shi, p_slo, p_wvh, p_wvl, p_v, nullptr, nullptr,
        B_ * NS_, INNER_, SD_, nullptr, nullptr, 1.0f);
    vtsplit_kernel<<<dim3(32, 32, B_), dim3(32, 8)>>>();

    // 4) scores (tensor)
    scores_mma<<<dim3(NS_ / 128, NC_ / 128, B_ * H_), 256, 4 * STILE_B>>>();
    // 5) softmax -> probs hi/lo bf16 in place
    softmax_kernel<<<B_ * H_ * NC_, 256>>>();
    // 6) head-mean -> second output
    attn_mean_kernel<<<B_ * NC_ * NS_ / 4 / 256, 256>>>(out_attn);
    // 7) av (tensor) -> bf16 hi/lo
    av_mma<<<dim3(NC_ / 128, B_ * H_), 256, AV_SMEM>>>();
    // 8) O proj + bias + residual
    gemm_mma<<<dim3(CD_ / 128, B_ * NC_ / 128), 256, GSMEM_B>>>(
        p_avh, p_avl, p_woh, p_wol, p_x, nullptr, nullptr,
        B_ * NC_, CD_, INNER_, bo, content, 1.0f);
    // 9) LayerNorm -> first output
    ln_kernel<<<B_ * NC_, 256>>>(gamma, beta, out);
}

// round 7
// speedup vs baseline: 2.3584x; 1.0830x over previous
#include <cuda_runtime.h>
#include <cuda_bf16.h>
#include <math.h>
#include <stdint.h>

#define B_    4
#define NC_   4096
#define NS_   1024
#define CD_   1024
#define SD_   768
#define H_    16
#define D_    64
#define INNER_ 1024
#define LN_EPS 1e-5f

// ---------------- static device scratch ----------------
__device__ float g_attn[(size_t)B_ * H_ * NC_ * NS_];   // probs bf16 hi/lo rows (4 KB/row)
__device__ float g_x[(size_t)B_ * NC_ * CD_];
__device__ float g_v[(size_t)B_ * NS_ * INNER_];

__device__ __nv_bfloat16 g_c_hi[(size_t)B_ * NC_ * CD_];
__device__ __nv_bfloat16 g_c_lo[(size_t)B_ * NC_ * CD_];
__device__ __nv_bfloat16 g_s_hi[(size_t)B_ * NS_ * SD_];
__device__ __nv_bfloat16 g_s_lo[(size_t)B_ * NS_ * SD_];
__device__ __nv_bfloat16 g_qh[(size_t)B_ * NC_ * INNER_];   // Q (pre-scaled 1/8) hi/lo
__device__ __nv_bfloat16 g_ql[(size_t)B_ * NC_ * INNER_];
__device__ __nv_bfloat16 g_kh[(size_t)B_ * NS_ * INNER_];
__device__ __nv_bfloat16 g_kl[(size_t)B_ * NS_ * INNER_];
__device__ __nv_bfloat16 g_vth[(size_t)B_ * INNER_ * NS_];  // V^T per head [z*64+d][s]
__device__ __nv_bfloat16 g_vtl[(size_t)B_ * INNER_ * NS_];
__device__ __nv_bfloat16 g_avh[(size_t)B_ * NC_ * INNER_];
__device__ __nv_bfloat16 g_avl[(size_t)B_ * NC_ * INNER_];

__device__ __nv_bfloat16 g_wqt_hi[INNER_ * CD_];
__device__ __nv_bfloat16 g_wqt_lo[INNER_ * CD_];
__device__ __nv_bfloat16 g_wkt_hi[INNER_ * SD_];
__device__ __nv_bfloat16 g_wkt_lo[INNER_ * SD_];
__device__ __nv_bfloat16 g_wvt_hi[INNER_ * SD_];
__device__ __nv_bfloat16 g_wvt_lo[INNER_ * SD_];
__device__ __nv_bfloat16 g_wot_hi[CD_ * INNER_];
__device__ __nv_bfloat16 g_wot_lo[CD_ * INNER_];

// ================= helpers =================
__device__ __forceinline__ uint32_t smem_u32(const void* p) {
    uint32_t a;
    asm("{ .reg .u64 t; cvta.to.shared.u64 t, %1; cvt.u32.u64 %0, t; }" : "=r"(a) : "l"(p));
    return a;
}
__device__ __forceinline__ void ldsm_x4(uint32_t* f, uint32_t addr) {
    asm volatile("ldmatrix.sync.aligned.m8n8.x4.shared.b16 {%0,%1,%2,%3}, [%4];"
                 : "=r"(f[0]), "=r"(f[1]), "=r"(f[2]), "=r"(f[3]) : "r"(addr));
}
__device__ __forceinline__ void ldsm_x2(uint32_t* f, uint32_t addr) {
    asm volatile("ldmatrix.sync.aligned.m8n8.x2.shared.b16 {%0,%1}, [%2];"
                 : "=r"(f[0]), "=r"(f[1]) : "r"(addr));
}
__device__ __forceinline__ void mma_bf16(float* c, const uint32_t* a, const uint32_t* b) {
    asm volatile("mma.sync.aligned.m16n8k16.row.col.f32.bf16.bf16.f32 "
                 "{%0,%1,%2,%3}, {%4,%5,%6,%7}, {%8,%9}, {%0,%1,%2,%3};"
                 : "+f"(c[0]), "+f"(c[1]), "+f"(c[2]), "+f"(c[3])
                 : "r"(a[0]), "r"(a[1]), "r"(a[2]), "r"(a[3]), "r"(b[0]), "r"(b[1]));
}
__device__ __forceinline__ void split2(float x, float y, uint32_t& hp, uint32_t& lp) {
    __nv_bfloat16 hx = __float2bfloat16(x), hy = __float2bfloat16(y);
    hp = ((uint32_t)*(uint16_t*)&hy << 16) | *(uint16_t*)&hx;
    __nv_bfloat16 lx = __float2bfloat16(x - __bfloat162float(hx));
    __nv_bfloat16 ly = __float2bfloat16(y - __bfloat162float(hy));
    lp = ((uint32_t)*(uint16_t*)&ly << 16) | *(uint16_t*)&lx;
}

// ================================================================
// Generic bf16-split GEMM (validated R4/R5)
// ================================================================
#define TILE_B   10240
#define BUF_B    (4 * TILE_B)
#define GSMEM_B  (2 * BUF_B)

__global__ void __launch_bounds__(256, 1) gemm_mma(
    const __nv_bfloat16* __restrict__ Ah, const __nv_bfloat16* __restrict__ Al,
    const __nv_bfloat16* __restrict__ Bh, const __nv_bfloat16* __restrict__ Bl,
    float* __restrict__ C, __nv_bfloat16* __restrict__ Oh, __nv_bfloat16* __restrict__ Ol,
    int M, int N, int K,
    const float* __restrict__ bias, const float* __restrict__ resid, float alpha)
{
    extern __shared__ char sm[];
    const int tid = threadIdx.x;
    const int lane = tid & 31;
    const int wid = tid >> 5;
    const int bm = blockIdx.y * 128;
    const int bn = blockIdx.x * 128;
    const int nch = K >> 5;

    const int wm = (wid >> 2) * 64;
    const int wn = (wid & 3) * 32;

    const uint32_t sA = smem_u32(sm);
    const uint32_t a_off = (uint32_t)(lane & 15) * 80 + (uint32_t)(lane >> 4) * 16;
    const uint32_t b_off = (uint32_t)(lane & 7) * 80 + (uint32_t)((lane >> 3) & 1) * 16;

    float acc[4][4][4];
#pragma unroll
    for (int mt = 0; mt < 4; mt++)
#pragma unroll
        for (int nt = 0; nt < 4; nt++)
#pragma unroll
            for (int r = 0; r < 4; r++) acc[mt][nt][r] = 0.f;

#pragma unroll
    for (int it = 0; it < 8; it++) {
        const int idx = (it << 8) + tid;
        const int t = idx >> 9;
        const int r = (idx >> 2) & 127;
        const int s = idx & 3;
        const __nv_bfloat16* src = (t == 0) ? Ah : (t == 1) ? Al : (t == 2) ? Bh : Bl;
        const int rb = (t < 2) ? bm : bn;
        uint4 v = *(const uint4*)(src + (size_t)(rb + r) * K + s * 8);
        *(uint4*)(sm + t * TILE_B + r * 80 + s * 16) = v;
    }
    __syncthreads();

    for (int c = 0; c < nch; c++) {
        uint4 g[8];
        if (c + 1 < nch) {
            const int ko = (c + 1) << 5;
#pragma unroll
            for (int it = 0; it < 8; it++) {
                const int idx = (it << 8) + tid;
                const int t = idx >> 9;
                const int r = (idx >> 2) & 127;
                const int s = idx & 3;
                const __nv_bfloat16* src = (t == 0) ? Ah : (t == 1) ? Al : (t == 2) ? Bh : Bl;
                const int rb = (t < 2) ? bm : bn;
                g[it] = *(const uint4*)(src + (size_t)(rb + r) * K + ko + s * 8);
            }
        }
        {
            const uint32_t base = sA + (uint32_t)(c & 1) * BUF_B;
#pragma unroll
            for (int kk = 0; kk < 2; kk++) {
                const uint32_t ko = kk * 32;
                uint32_t bh[4][2], bl[4][2];
#pragma unroll
                for (int nt = 0; nt < 4; nt++) {
                    ldsm_x2(bh[nt], base + 2 * TILE_B + (uint32_t)(wn + nt * 8) * 80 + b_off + ko);
                    ldsm_x2(bl[nt], base + 3 * TILE_B + (uint32_t)(wn + nt * 8) * 80 + b_off + ko);
                }
#pragma unroll
                for (int mt = 0; mt < 4; mt++) {
                    uint32_t ah[4], al[4];
                    ldsm_x4(ah, base + (uint32_t)(wm + mt * 16) * 80 + a_off + ko);
                    ldsm_x4(al, base + TILE_B + (uint32_t)(wm + mt * 16) * 80 + a_off + ko);
#pragma unroll
                    for (int nt = 0; nt < 4; nt++) {
                        mma_bf16(acc[mt][nt], ah, bh[nt]);
                        mma_bf16(acc[mt][nt], ah, bl[nt]);
                        mma_bf16(acc[mt][nt], al, bh[nt]);
                    }
                }
            }
        }
        if (c + 1 < nch) {
            char* dst = sm + ((c + 1) & 1) * BUF_B;
#pragma unroll
            for (int it = 0; it < 8; it++) {
                const int idx = (it << 8) + tid;
                const int t = idx >> 9;
                const int r = (idx >> 2) & 127;
                const int s = idx & 3;
                *(uint4*)(dst + t * TILE_B + r * 80 + s * 16) = g[it];
            }
        }
        __syncthreads();
    }

#pragma unroll
    for (int mt = 0; mt < 4; mt++) {
        const int row0 = bm + wm + mt * 16 + (lane >> 2);
#pragma unroll
        for (int nt = 0; nt < 4; nt++) {
            const int col = bn + wn + nt * 8 + (lane & 3) * 2;
#pragma unroll
            for (int half = 0; half < 2; half++) {
                const int row = row0 + half * 8;
                float vx = acc[mt][nt][half * 2] * alpha;
                float vy = acc[mt][nt][half * 2 + 1] * alpha;
                if (Oh) {
                    uint32_t hp, lp;
                    split2(vx, vy, hp, lp);
                    *(uint32_t*)(Oh + (size_t)row * N + col) = hp;
                    *(uint32_t*)(Ol + (size_t)row * N + col) = lp;
                } else {
                    if (bias) { vx += bias[col]; vy += bias[col + 1]; }
                    if (resid) {
                        float2 t = *(const float2*)(resid + (size_t)row * N + col);
                        vx += t.x; vy += t.y;
                    }
                    *(float2*)(C + (size_t)row * N + col) = make_float2(vx, vy);
                }
            }
        }
    }
}

// ================================================================
// FUSED scores + softmax. per CTA = (z, 32 q rows), full NS=1024.
// Row stride for Q/K tiles is 144 B (= 64 bf16 data + 16 pad).  <-- R6 fix
// smem: Q 9216 + 2x K 36864 + scores 132096 = 215040 B.
// ================================================================
#define FS_QSP  4608              // one Q split: 32 x 144
#define FS_QT   (2 * FS_QSP)      // 9216
#define FS_KSP  18432             // one K split: 128 x 144
#define FS_KT   (2 * FS_KSP)      // 36864 per buffer
#define FS_SROW 4128
#define FS_SMEM (FS_QT + 2 * FS_KT + 32 * FS_SROW)   // 215040

__global__ void __launch_bounds__(256, 1) fused_attn_probs()
{
    extern __shared__ char sm[];
    const int tid = threadIdx.x;
    const int lane = tid & 31;
    const int wid = tid >> 5;
    const int z = blockIdx.y;
    const int b = z >> 4;
    const int h = z & 15;
    const int q0 = b * NC_ + blockIdx.x * 32;
    const int kb = b * NS_;

    char* smQ = sm;
    char* smK = sm + FS_QT;
    char* smS = sm + FS_QT + 2 * FS_KT;
    const uint32_t uQ = smem_u32(smQ);
    const uint32_t uK = smem_u32(smK);

    // Q tile: 2 splits x 32 rows x 8 segs = 512 uint4 items
#pragma unroll
    for (int it = 0; it < 2; it++) {
        const int idx = (it << 8) + tid;
        const int sp = idx >> 8;
        const int r = (idx >> 3) & 31;
        const int s = idx & 7;
        const __nv_bfloat16* src = sp ? g_ql : g_qh;
        uint4 v = *(const uint4*)(src + (size_t)(q0 + r) * INNER_ + h * 64 + s * 8);
        *(uint4*)(smQ + sp * FS_QSP + r * 144 + s * 16) = v;
    }
    // K chunk 0: 2 splits x 128 rows x 8 segs = 2048 items
#pragma unroll
    for (int it = 0; it < 8; it++) {
        const int idx = (it << 8) + tid;
        const int sp = idx >> 10;
        const int r = (idx >> 3) & 127;
        const int s = idx & 7;
        const __nv_bfloat16* src = sp ? g_kl : g_kh;
        uint4 v = *(const uint4*)(src + (size_t)(kb + r) * INNER_ + h * 64 + s * 8);
        *(uint4*)(smK + sp * FS_KSP + r * 144 + s * 16) = v;
    }
    __syncthreads();

    const int wm = (wid >> 2) * 16;
    const int wn = (wid & 3) * 32;
    const uint32_t a_off = (uint32_t)(lane & 15) * 144 + (uint32_t)(lane >> 4) * 16;
    const uint32_t b_off = (uint32_t)(lane & 7) * 144 + (uint32_t)((lane >> 3) & 1) * 16;

    for (int kc = 0; kc < 8; kc++) {
        uint4 g[8];
        if (kc + 1 < 8) {
            const int krow = kb + (kc + 1) * 128;
#pragma unroll
            for (int it = 0; it < 8; it++) {
                const int idx = (it << 8) + tid;
                const int sp = idx >> 10;
                const int r = (idx >> 3) & 127;
                const int s = idx & 7;
                const __nv_bfloat16* src = sp ? g_kl : g_kh;
                g[it] = *(const uint4*)(src + (size_t)(krow + r) * INNER_ + h * 64 + s * 8);
            }
        }
        float acc[4][4];
#pragma unroll
        for (int nt = 0; nt < 4; nt++)
#pragma unroll
            for (int r = 0; r < 4; r++) acc[nt][r] = 0.f;

        const uint32_t kbuf = uK + (uint32_t)(kc & 1) * FS_KT;
#pragma unroll
        for (int kk = 0; kk < 4; kk++) {
            const uint32_t ko = kk * 32;
            uint32_t ah[4], al[4];
            ldsm_x4(ah, uQ + (uint32_t)wm * 144 + a_off + ko);
            ldsm_x4(al, uQ + FS_QSP + (uint32_t)wm * 144 + a_off + ko);
            uint32_t bh[4][2], bl[4][2];
#pragma unroll
            for (int nt = 0; nt < 4; nt++) {
                ldsm_x2(bh[nt], kbuf + (uint32_t)(wn + nt * 8) * 144 + b_off + ko);
                ldsm_x2(bl[nt], kbuf + FS_KSP + (uint32_t)(wn + nt * 8) * 144 + b_off + ko);
            }
#pragma unroll
            for (int nt = 0; nt < 4; nt++) {
                mma_bf16(acc[nt], ah, bh[nt]);
                mma_bf16(acc[nt], ah, bl[nt]);
                mma_bf16(acc[nt], al, bh[nt]);
            }
        }
        // scores chunk -> smem fp32
#pragma unroll
        for (int nt = 0; nt < 4; nt++) {
            const int col = kc * 128 + wn + nt * 8 + (lane & 3) * 2;
#pragma unroll
            for (int half = 0; half < 2; half++) {
                const int row = wm + (lane >> 2) + half * 8;
                *(float2*)(smS + row * FS_SROW + col * 4) =
                    make_float2(acc[nt][half * 2], acc[nt][half * 2 + 1]);
            }
        }
        if (kc + 1 < 8) {
            char* dst = smK + ((kc + 1) & 1) * FS_KT;
#pragma unroll
            for (int it = 0; it < 8; it++) {
                const int idx = (it << 8) + tid;
                const int sp = idx >> 10;
                const int r = (idx >> 3) & 127;
                const int s = idx & 7;
                *(uint4*)(dst + sp * FS_KSP + r * 144 + s * 16) = g[it];
            }
        }
        __syncthreads();
    }

    // softmax: warp w -> rows w*4..w*4+3; write probs bf16 hi/lo to global
    char* gz = (char*)g_attn + ((((size_t)z << 12) + (size_t)blockIdx.x * 32) << 12);
#pragma unroll
    for (int rr = 0; rr < 4; rr++) {
        const int r = wid * 4 + rr;
        const char* rb = smS + r * FS_SROW + lane * 16;
        float4 v[8];
#pragma unroll
        for (int it = 0; it < 8; it++) v[it] = *(const float4*)(rb + it * 512);

        float m = -1e30f;
#pragma unroll
        for (int it = 0; it < 8; it++)
            m = fmaxf(m, fmaxf(fmaxf(v[it].x, v[it].y), fmaxf(v[it].z, v[it].w)));
#pragma unroll
        for (int o = 16; o; o >>= 1) m = fmaxf(m, __shfl_xor_sync(0xffffffffu, m, o));

        float s = 0.f;
#pragma unroll
        for (int it = 0; it < 8; it++) {
            v[it].x = __expf(v[it].x - m); v[it].y = __expf(v[it].y - m);
            v[it].z = __expf(v[it].z - m); v[it].w = __expf(v[it].w - m);
            s += (v[it].x + v[it].y) + (v[it].z + v[it].w);
        }
#pragma unroll
        for (int o = 16; o; o >>= 1) s += __shfl_xor_sync(0xffffffffu, s, o);
        const float inv = 1.f / s;

        char* grow = gz + (size_t)r * 4096;
#pragma unroll
        for (int it = 0; it < 8; it++) {
            const float x = v[it].x * inv, y = v[it].y * inv;
            const float zz = v[it].z * inv, w = v[it].w * inv;
            uint32_t h0, l0, h1, l1;
            split2(x, y, h0, l0);
            split2(zz, w, h1, l1);
            const int cofs = (it * 128 + lane * 4) * 2;
            *(uint2*)(grow + cofs) = make_uint2(h0, h1);
            *(uint2*)(grow + 2048 + cofs) = make_uint2(l0, l1);
        }
    }
}

// ================================================================
// attn_mean from hi/lo bf16 probs
// ================================================================
__global__ void attn_mean_kernel(float* __restrict__ out2)
{
    const size_t idx = (size_t)blockIdx.x * 256 + threadIdx.x;
    const size_t e0 = idx << 2;
    const int b = (int)(e0 >> 22);
    const int q = (int)((e0 >> 10) & 4095);
    const int k = (int)(e0 & 1023);
    const __nv_bfloat16* pb = (const __nv_bfloat16*)g_attn;

    float s0 = 0.f, s1 = 0.f, s2 = 0.f, s3 = 0.f;
#pragma unroll
    for (int h = 0; h < H_; h++) {
        const size_t row = ((size_t)(b * H_ + h) << 12) + q;
        const __nv_bfloat16* ph = pb + row * 2048 + k;
        uint2 hv = *(const uint2*)ph;
        uint2 lv = *(const uint2*)(ph + 1024);
        float2 h0 = __bfloat1622float2(*(__nv_bfloat162*)&hv.x);
        float2 h1 = __bfloat1622float2(*(__nv_bfloat162*)&hv.y);
        float2 l0 = __bfloat1622float2(*(__nv_bfloat162*)&lv.x);
        float2 l1 = __bfloat1622float2(*(__nv_bfloat162*)&lv.y);
        s0 += h0.x + l0.x; s1 += h0.y + l0.y;
        s2 += h1.x + l1.x; s3 += h1.y + l1.y;
    }
    const float c = 1.0f / 16.0f;
    *(float4*)(out2 + e0) = make_float4(s0 * c, s1 * c, s2 * c, s3 * c);
}

// ================================================================
// av_mma (validated R5)
// ================================================================
#define AV_AT   18432
#define AV_BT   9216
#define AV_BUF  (2 * AV_AT + 2 * AV_BT)
#define AV_SMEM (2 * AV_BUF)

__global__ void __launch_bounds__(256, 1) av_mma()
{
    extern __shared__ char sm[];
    const int tid = threadIdx.x;
    const int lane = tid & 31;
    const int wid = tid >> 5;
    const int by = blockIdx.x;
    const int z = blockIdx.y;
    const int b = z >> 4;
    const int h = z & 15;

    const int wm = (wid >> 2) * 64;
    const int wn = (wid & 3) * 16;
    const uint32_t sA = smem_u32(sm);
    const uint32_t a_off = (uint32_t)(lane & 15) * 144 + (uint32_t)(lane >> 4) * 16;
    const uint32_t b_off = (uint32_t)(lane & 7) * 144 + (uint32_t)((lane >> 3) & 1) * 16;

    const char* attn_bytes = (const char*)g_attn + ((((size_t)z << 12) + (size_t)by * 128) << 12);
    const __nv_bfloat16* vth = g_vth + (size_t)z * 64 * NS_;
    const __nv_bfloat16* vtl = g_vtl + (size_t)z * 64 * NS_;

    float acc[4][2][4];
#pragma unroll
    for (int mt = 0; mt < 4; mt++)
#pragma unroll
        for (int nt = 0; nt < 2; nt++)
#pragma unroll
            for (int r = 0; r < 4; r++) acc[mt][nt][r] = 0.f;

#define AV_LOAD_G(c_, gArr_)                                                          \
    {                                                                                 \
        const int cc = (c_);                                                          \
        _Pragma("unroll")                                                             \
        for (int it = 0; it < 12; it++) {                                             \
            const int item = (it << 8) + tid;                                         \
            if (item < 2048) {                                                        \
                const int half = item >> 10;                                          \
                const int r = (item >> 3) & 127;                                      \
                const int s = item & 7;                                               \
                gArr_[it] = *(const uint4*)(attn_bytes + ((size_t)r << 12)            \
                              + half * 2048 + cc * 128 + s * 16);                     \
            } else {                                                                  \
                const int i2 = item - 2048;                                           \
                const int half = i2 >> 9;                                             \
                const int r = (i2 >> 3) & 63;                                         \
                const int s = i2 & 7;                                                 \
                const __nv_bfloat16* src = half ? vtl : vth;                          \
                gArr_[it] = *(const uint4*)(src + (size_t)r * NS_ + cc * 64 + s * 8); \
            }                                                                         \
        }                                                                             \
    }
#define AV_STORE_S(buf_, gArr_)                                                       \
    {                                                                                 \
        char* dst = sm + (buf_) * AV_BUF;                                             \
        _Pragma("unroll")                                                             \
        for (int it = 0; it < 12; it++) {                                             \
            const int item = (it << 8) + tid;                                         \
            if (item < 2048) {                                                        \
                const int half = item >> 10;                                          \
                const int r = (item >> 3) & 127;                                      \
                const int s = item & 7;                                               \
                *(uint4*)(dst + half * AV_AT + r * 144 + s * 16) = gArr_[it];         \
            } else {                                                                  \
                const int i2 = item - 2048;                                           \
                const int half = i2 >> 9;                                             \
                const int r = (i2 >> 3) & 63;                                         \
                const int s = i2 & 7;                                                 \
                *(uint4*)(dst + 2 * AV_AT + half * AV_BT + r * 144 + s * 16) = gArr_[it]; \
            }                                                                         \
        }                                                                             \
    }

    {
        uint4 g[12];
        AV_LOAD_G(0, g);
        AV_STORE_S(0, g);
    }
    __syncthreads();

    for (int c = 0; c < 16; c++) {
        uint4 g[12];
        if (c + 1 < 16) AV_LOAD_G(c + 1, g);
        {
            const uint32_t base = sA + (uint32_t)(c & 1) * AV_BUF;
#pragma unroll
            for (int kk = 0; kk < 4; kk++) {
                const uint32_t ko = kk * 32;
                uint32_t bh[2][2], bl[2][2];
#pragma unroll
                for (int nt = 0; nt < 2; nt++) {
                    ldsm_x2(bh[nt], base + 2 * AV_AT + (uint32_t)(wn + nt * 8) * 144 + b_off + ko);
                    ldsm_x2(bl[nt], base + 2 * AV_AT + AV_BT + (uint32_t)(wn + nt * 8) * 144 + b_off + ko);
                }
#pragma unroll
                for (int mt = 0; mt < 4; mt++) {
                    uint32_t ah[4], al[4];
                    ldsm_x4(ah, base + (uint32_t)(wm + mt * 16) * 144 + a_off + ko);
                    ldsm_x4(al, base + AV_AT + (uint32_t)(wm + mt * 16) * 144 + a_off + ko);
#pragma unroll
                    for (int nt = 0; nt < 2; nt++) {
                        mma_bf16(acc[mt][nt], ah, bh[nt]);
                        mma_bf16(acc[mt][nt], ah, bl[nt]);
                        mma_bf16(acc[mt][nt], al, bh[nt]);
                    }
                }
            }
        }
        if (c + 1 < 16) AV_STORE_S((c + 1) & 1, g);
        __syncthreads();
    }

#pragma unroll
    for (int mt = 0; mt < 4; mt++) {
        const int row0 = b * NC_ + by * 128 + wm + mt * 16 + (lane >> 2);
#pragma unroll
        for (int nt = 0; nt < 2; nt++) {
            const int col = h * 64 + wn + nt * 8 + (lane & 3) * 2;
#pragma unroll
            for (int half = 0; half < 2; half++) {
                const int row = row0 + half * 8;
                uint32_t hp, lp;
                split2(acc[mt][nt][half * 2], acc[mt][nt][half * 2 + 1], hp, lp);
                *(uint32_t*)(g_avh + (size_t)row * INNER_ + col) = hp;
                *(uint32_t*)(g_avl + (size_t)row * INNER_ + col) = lp;
            }
        }
    }
}

// ================================================================
// fp32 -> bf16 hi/lo split
// ================================================================
__global__ void split_kernel(const float4* __restrict__ in,
                             uint2* __restrict__ oh, uint2* __restrict__ ol, int n4)
{
    const int i = blockIdx.x * 256 + threadIdx.x;
    if (i >= n4) return;
    float4 v = in[i];
    __align__(8) __nv_bfloat16 h[4], l[4];
    const float f[4] = {v.x, v.y, v.z, v.w};
#pragma unroll
    for (int j = 0; j < 4; j++) {
        h[j] = __float2bfloat16(f[j]);
        l[j] = __float2bfloat16(f[j] - __bfloat162float(h[j]));
    }
    oh[i] = *(uint2*)h;
    ol[i] = *(uint2*)l;
}

// ================================================================
// Transpose + split weights
// ================================================================
__global__ void tsplit_kernel(const float* __restrict__ in,
                              __nv_bfloat16* __restrict__ oh,
                              __nv_bfloat16* __restrict__ ol, int R, int Ncol)
{
    __shared__ float t[32][33];
    const int bx = blockIdx.x * 32, by = blockIdx.y * 32;
    const int tx = threadIdx.x, ty = threadIdx.y;
#pragma unroll
    for (int i = 0; i < 32; i += 8)
        t[ty + i][tx] = in[(size_t)(by + ty + i) * Ncol + bx + tx];
    __syncthreads();
#pragma unroll
    for (int i = 0; i < 32; i += 8) {
        const float v = t[tx][ty + i];
        const size_t o = (size_t)(bx + ty + i) * R + by + tx;
        __nv_bfloat16 h = __float2bfloat16(v);
        oh[o] = h;
        ol[o] = __float2bfloat16(v - __bfloat162float(h));
    }
}

// ================================================================
// V^T split
// ================================================================
__global__ void vtsplit_kernel()
{
    __shared__ float t[32][33];
    const int b = blockIdx.z;
    const int bx = blockIdx.x * 32;
    const int by = blockIdx.y * 32;
    const int tx = threadIdx.x, ty = threadIdx.y;
    const float* in = g_v + (size_t)b * NS_ * INNER_;
#pragma unroll
    for (int i = 0; i < 32; i += 8)
        t[ty + i][tx] = in[(size_t)(by + ty + i) * INNER_ + bx + tx];
    __syncthreads();
#pragma unroll
    for (int i = 0; i < 32; i += 8) {
        const float v = t[tx][ty + i];
        const size_t o = (size_t)(b * 1024 + bx + ty + i) * NS_ + by + tx;
        __nv_bfloat16 h = __float2bfloat16(v);
        g_vth[o] = h;
        g_vtl[o] = __float2bfloat16(v - __bfloat162float(h));
    }
}

// ================================================================
// LayerNorm
// ================================================================
__global__ void ln_kernel(const float* __restrict__ gamma,
                          const float* __restrict__ beta,
                          float* __restrict__ out)
{
    __shared__ float reds[9];
    __shared__ float redq[9];
    const size_t row = blockIdx.x;
    const int tid = threadIdx.x;

    float4 x = reinterpret_cast<const float4*>(g_x + row * CD_)[tid];
    float s = x.x + x.y + x.z + x.w;
    float q = x.x * x.x + x.y * x.y + x.z * x.z + x.w * x.w;
#pragma unroll
    for (int o = 16; o; o >>= 1) {
        s += __shfl_xor_sync(0xffffffffu, s, o);
        q += __shfl_xor_sync(0xffffffffu, q, o);
    }
    if ((tid & 31) == 0) { reds[tid >> 5] = s; redq[tid >> 5] = q; }
    __syncthreads();
    if (tid == 0) {
        float ss = 0.f, qq = 0.f;
#pragma unroll
        for (int i = 0; i < 8; i++) { ss += reds[i]; qq += redq[i]; }
        reds[8] = ss; redq[8] = qq;
    }
    __syncthreads();
    const float mu = reds[8] * (1.0f / 1024.0f);
    const float var = redq[8] * (1.0f / 1024.0f) - mu * mu;
    const float rstd = rsqrtf(var + LN_EPS);

    float4 g = reinterpret_cast<const float4*>(gamma)[tid];
    float4 bb = reinterpret_cast<const float4*>(beta)[tid];
    float4 r;
    r.x = (x.x - mu) * rstd * g.x + bb.x;
    r.y = (x.y - mu) * rstd * g.y + bb.y;
    r.z = (x.z - mu) * rstd * g.z + bb.z;
    r.w = (x.w - mu) * rstd * g.w + bb.w;
    reinterpret_cast<float4*>(out + row * CD_)[tid] = r;
}

// ================================================================
extern "C" void kernel_launch(void* const* d_in, const int* in_sizes, int n_in,
                              void* d_out, int out_size)
{
    const float* content = (const float*)d_in[0];
    const float* style   = (const float*)d_in[1];
    const float* Wq      = (const float*)d_in[2];
    const float* Wk      = (const float*)d_in[3];
    const float* Wv      = (const float*)d_in[4];
    const float* Wo      = (const float*)d_in[5];
    const float* bo      = (const float*)d_in[6];
    const float* gamma   = (const float*)d_in[7];
    const float* beta    = (const float*)d_in[8];
    float* out = (float*)d_out;
    float* out_attn = out + (size_t)B_ * NC_ * CD_;

    cudaFuncSetAttribute(gemm_mma, cudaFuncAttributeMaxDynamicSharedMemorySize, GSMEM_B);
    cudaFuncSetAttribute(fused_attn_probs, cudaFuncAttributeMaxDynamicSharedMemorySize, FS_SMEM);
    cudaFuncSetAttribute(av_mma, cudaFuncAttributeMaxDynamicSharedMemorySize, AV_SMEM);

    float *p_v, *p_x;
    __nv_bfloat16 *p_chi, *p_clo, *p_shi, *p_slo, *p_avh, *p_avl;
    __nv_bfloat16 *p_qh, *p_ql, *p_kh, *p_kl;
    __nv_bfloat16 *p_wqh, *p_wql, *p_wkh, *p_wkl, *p_wvh, *p_wvl, *p_woh, *p_wol;
    cudaGetSymbolAddress((void**)&p_v,   g_v);
    cudaGetSymbolAddress((void**)&p_x,   g_x);
    cudaGetSymbolAddress((void**)&p_chi, g_c_hi);
    cudaGetSymbolAddress((void**)&p_clo, g_c_lo);
    cudaGetSymbolAddress((void**)&p_shi, g_s_hi);
    cudaGetSymbolAddress((void**)&p_slo, g_s_lo);
    cudaGetSymbolAddress((void**)&p_qh,  g_qh);
    cudaGetSymbolAddress((void**)&p_ql,  g_ql);
    cudaGetSymbolAddress((void**)&p_kh,  g_kh);
    cudaGetSymbolAddress((void**)&p_kl,  g_kl);
    cudaGetSymbolAddress((void**)&p_avh, g_avh);
    cudaGetSymbolAddress((void**)&p_avl, g_avl);
    cudaGetSymbolAddress((void**)&p_wqh, g_wqt_hi);
    cudaGetSymbolAddress((void**)&p_wql, g_wqt_lo);
    cudaGetSymbolAddress((void**)&p_wkh, g_wkt_hi);
    cudaGetSymbolAddress((void**)&p_wkl, g_wkt_lo);
    cudaGetSymbolAddress((void**)&p_wvh, g_wvt_hi);
    cudaGetSymbolAddress((void**)&p_wvl, g_wvt_lo);
    cudaGetSymbolAddress((void**)&p_woh, g_wot_hi);
    cudaGetSymbolAddress((void**)&p_wol, g_wot_lo);

    // 0) splits
    split_kernel<<<(B_ * NC_ * CD_ / 4 + 255) / 256, 256>>>(
        (const float4*)content, (uint2*)p_chi, (uint2*)p_clo, B_ * NC_ * CD_ / 4);
    split_kernel<<<(B_ * NS_ * SD_ / 4 + 255) / 256, 256>>>(
        (const float4*)style, (uint2*)p_shi, (uint2*)p_slo, B_ * NS_ * SD_ / 4);
    tsplit_kernel<<<dim3(32, 32), dim3(32, 8)>>>(Wq, p_wqh, p_wql, CD_, INNER_);
    tsplit_kernel<<<dim3(32, 24), dim3(32, 8)>>>(Wk, p_wkh, p_wkl, SD_, INNER_);
    tsplit_kernel<<<dim3(32, 24), dim3(32, 8)>>>(Wv, p_wvh, p_wvl, SD_, INNER_);
    tsplit_kernel<<<dim3(32, 32), dim3(32, 8)>>>(Wo, p_woh, p_wol, INNER_, CD_);

    // 1) Q proj -> bf16 hi/lo (pre-scaled 1/8)
    gemm_mma<<<dim3(INNER_ / 128, B_ * NC_ / 128), 256, GSMEM_B>>>(
        p_chi, p_clo, p_wqh, p_wql, nullptr, p_qh, p_ql,
        B_ * NC_, INNER_, CD_, nullptr, nullptr, 0.125f);
    // 2) K proj -> bf16 hi/lo
    gemm_mma<<<dim3(INNER_ / 128, B_ * NS_ / 128), 256, GSMEM_B>>>(
        p_shi, p_slo, p_wkh, p_wkl, nullptr, p_kh, p_kl,
        B_ * NS_, INNER_, SD_, nullptr, nullptr, 1.0f);
    // 3) V proj -> fp32, then per-head transpose+split
    gemm_mma<<<dim3(INNER_ / 128, B_ * NS_ / 128), 256, GSMEM_B>>>(
        p_shi, p_slo, p_wvh, p_wvl, p_v, nullptr, nullptr,
        B_ * NS_, INNER_, SD_, nullptr, nullptr, 1.0f);
    vtsplit_kernel<<<dim3(32, 32, B_), dim3(32, 8)>>>();

    // 4) FUSED scores + softmax -> probs bf16 hi/lo in g_attn
    fused_attn_probs<<<dim3(NC_ / 32, B_ * H_), 256, FS_SMEM>>>();
    // 5) head-mean -> second output
    attn_mean_kernel<<<B_ * NC_ * NS_ / 4 / 256, 256>>>(out_attn);
    // 6) av (tensor) -> bf16 hi/lo
    av_mma<<<dim3(NC_ / 128, B_ * H_), 256, AV_SMEM>>>();
    // 7) O proj + bias + residual
    gemm_mma<<<dim3(CD_ / 128, B_ * NC_ / 128), 256, GSMEM_B>>>(
        p_avh, p_avl, p_woh, p_wol, p_x, nullptr, nullptr,
        B_ * NC_, CD_, INNER_, bo, content, 1.0f);
    // 8) LayerNorm -> first output
    ln_kernel<<<B_ * NC_, 256>>>(gamma, beta, out);
}

// round 9
// speedup vs baseline: 2.6592x; 1.1276x over previous
#include <cuda_runtime.h>
#include <cuda_bf16.h>
#include <math.h>
#include <stdint.h>

#define B_    4
#define NC_   4096
#define NS_   1024
#define CD_   1024
#define SD_   768
#define H_    16
#define D_    64
#define INNER_ 1024
#define LN_EPS 1e-5f

// ---------------- static device scratch ----------------
__device__ float g_attn[(size_t)B_ * H_ * NC_ * NS_];   // probs bf16 hi/lo rows (4 KB/row)
__device__ float g_x[(size_t)B_ * NC_ * CD_];
__device__ float g_v[(size_t)B_ * NS_ * INNER_];

__device__ __nv_bfloat16 g_c_hi[(size_t)B_ * NC_ * CD_];
__device__ __nv_bfloat16 g_c_lo[(size_t)B_ * NC_ * CD_];
__device__ __nv_bfloat16 g_s_hi[(size_t)B_ * NS_ * SD_];
__device__ __nv_bfloat16 g_s_lo[(size_t)B_ * NS_ * SD_];
__device__ __nv_bfloat16 g_qh[(size_t)B_ * NC_ * INNER_];   // Q (pre-scaled 1/8) hi/lo
__device__ __nv_bfloat16 g_ql[(size_t)B_ * NC_ * INNER_];
__device__ __nv_bfloat16 g_kh[(size_t)B_ * NS_ * INNER_];
__device__ __nv_bfloat16 g_kl[(size_t)B_ * NS_ * INNER_];
__device__ __nv_bfloat16 g_vth[(size_t)B_ * INNER_ * NS_];  // V^T per head [z*64+d][s], hi only
__device__ __nv_bfloat16 g_avh[(size_t)B_ * NC_ * INNER_];  // attended, hi only

__device__ __nv_bfloat16 g_wqt_hi[INNER_ * CD_];
__device__ __nv_bfloat16 g_wqt_lo[INNER_ * CD_];
__device__ __nv_bfloat16 g_wkt_hi[INNER_ * SD_];
__device__ __nv_bfloat16 g_wkt_lo[INNER_ * SD_];
__device__ __nv_bfloat16 g_wvt_hi[INNER_ * SD_];
__device__ __nv_bfloat16 g_wvt_lo[INNER_ * SD_];
__device__ __nv_bfloat16 g_wot_hi[CD_ * INNER_];

// ================= helpers =================
__device__ __forceinline__ uint32_t smem_u32(const void* p) {
    uint32_t a;
    asm("{ .reg .u64 t; cvta.to.shared.u64 t, %1; cvt.u32.u64 %0, t; }" : "=r"(a) : "l"(p));
    return a;
}
__device__ __forceinline__ void ldsm_x4(uint32_t* f, uint32_t addr) {
    asm volatile("ldmatrix.sync.aligned.m8n8.x4.shared.b16 {%0,%1,%2,%3}, [%4];"
                 : "=r"(f[0]), "=r"(f[1]), "=r"(f[2]), "=r"(f[3]) : "r"(addr));
}
__device__ __forceinline__ void ldsm_x2(uint32_t* f, uint32_t addr) {
    asm volatile("ldmatrix.sync.aligned.m8n8.x2.shared.b16 {%0,%1}, [%2];"
                 : "=r"(f[0]), "=r"(f[1]) : "r"(addr));
}
__device__ __forceinline__ void mma_bf16(float* c, const uint32_t* a, const uint32_t* b) {
    asm volatile("mma.sync.aligned.m16n8k16.row.col.f32.bf16.bf16.f32 "
                 "{%0,%1,%2,%3}, {%4,%5,%6,%7}, {%8,%9}, {%0,%1,%2,%3};"
                 : "+f"(c[0]), "+f"(c[1]), "+f"(c[2]), "+f"(c[3])
                 : "r"(a[0]), "r"(a[1]), "r"(a[2]), "r"(a[3]), "r"(b[0]), "r"(b[1]));
}
__device__ __forceinline__ void split2(float x, float y, uint32_t& hp, uint32_t& lp) {
    __nv_bfloat16 hx = __float2bfloat16(x), hy = __float2bfloat16(y);
    hp = ((uint32_t)*(uint16_t*)&hy << 16) | *(uint16_t*)&hx;
    __nv_bfloat16 lx = __float2bfloat16(x - __bfloat162float(hx));
    __nv_bfloat16 ly = __float2bfloat16(y - __bfloat162float(hy));
    lp = ((uint32_t)*(uint16_t*)&ly << 16) | *(uint16_t*)&lx;
}
__device__ __forceinline__ uint32_t pack2(float x, float y) {
    __nv_bfloat16 hx = __float2bfloat16(x), hy = __float2bfloat16(y);
    return ((uint32_t)*(uint16_t*)&hy << 16) | *(uint16_t*)&hx;
}

// ================================================================
// Templated bf16-split GEMM.  TERMS=3: Ah*Bh + Ah*Bl + Al*Bh.
// TERMS=1: Ah*Bh only.
// 128x128 tile, BK=32, 256 thr = 8 warps (2Mx4N, 64x32 each), dbuf smem.
// ================================================================
#define TILE_B   10240
#define BUF_B    (4 * TILE_B)
#define GSMEM_B  (2 * BUF_B)

template <int TERMS>
__global__ void __launch_bounds__(256, 1) gemm_mma(
    const __nv_bfloat16* __restrict__ Ah, const __nv_bfloat16* __restrict__ Al,
    const __nv_bfloat16* __restrict__ Bh, const __nv_bfloat16* __restrict__ Bl,
    float* __restrict__ C, __nv_bfloat16* __restrict__ Oh, __nv_bfloat16* __restrict__ Ol,
    int M, int N, int K,
    const float* __restrict__ bias, const float* __restrict__ resid, float alpha)
{
    extern __shared__ char sm[];
    const int tid = threadIdx.x;
    const int lane = tid & 31;
    const int wid = tid >> 5;
    const int bm = blockIdx.y * 128;
    const int bn = blockIdx.x * 128;
    const int nch = K >> 5;
    const int NIT = (TERMS == 3) ? 8 : 4;

    const int wm = (wid >> 2) * 64;
    const int wn = (wid & 3) * 32;

    const uint32_t sA = smem_u32(sm);
    const uint32_t a_off = (uint32_t)(lane & 15) * 80 + (uint32_t)(lane >> 4) * 16;
    const uint32_t b_off = (uint32_t)(lane & 7) * 80 + (uint32_t)((lane >> 3) & 1) * 16;

    float acc[4][4][4];
#pragma unroll
    for (int mt = 0; mt < 4; mt++)
#pragma unroll
        for (int nt = 0; nt < 4; nt++)
#pragma unroll
            for (int r = 0; r < 4; r++) acc[mt][nt][r] = 0.f;

#pragma unroll
    for (int it = 0; it < NIT; it++) {
        const int idx = (it << 8) + tid;
        const int t = (TERMS == 3) ? (idx >> 9) : ((idx >> 9) * 2);
        const int r = (idx >> 2) & 127;
        const int s = idx & 3;
        const __nv_bfloat16* src = (t == 0) ? Ah : (t == 1) ? Al : (t == 2) ? Bh : Bl;
        const int rb = (t < 2) ? bm : bn;
        uint4 v = *(const uint4*)(src + (size_t)(rb + r) * K + s * 8);
        *(uint4*)(sm + t * TILE_B + r * 80 + s * 16) = v;
    }
    __syncthreads();

    for (int c = 0; c < nch; c++) {
        uint4 g[8];
        if (c + 1 < nch) {
            const int ko = (c + 1) << 5;
#pragma unroll
            for (int it = 0; it < NIT; it++) {
                const int idx = (it << 8) + tid;
                const int t = (TERMS == 3) ? (idx >> 9) : ((idx >> 9) * 2);
                const int r = (idx >> 2) & 127;
                const int s = idx & 3;
                const __nv_bfloat16* src = (t == 0) ? Ah : (t == 1) ? Al : (t == 2) ? Bh : Bl;
                const int rb = (t < 2) ? bm : bn;
                g[it] = *(const uint4*)(src + (size_t)(rb + r) * K + ko + s * 8);
            }
        }
        {
            const uint32_t base = sA + (uint32_t)(c & 1) * BUF_B;
#pragma unroll
            for (int kk = 0; kk < 2; kk++) {
                const uint32_t ko = kk * 32;
                uint32_t bh[4][2], bl[4][2];
#pragma unroll
                for (int nt = 0; nt < 4; nt++) {
                    ldsm_x2(bh[nt], base + 2 * TILE_B + (uint32_t)(wn + nt * 8) * 80 + b_off + ko);
                    if (TERMS == 3)
                        ldsm_x2(bl[nt], base + 3 * TILE_B + (uint32_t)(wn + nt * 8) * 80 + b_off + ko);
                }
#pragma unroll
                for (int mt = 0; mt < 4; mt++) {
                    uint32_t ah[4], al[4];
                    ldsm_x4(ah, base + (uint32_t)(wm + mt * 16) * 80 + a_off + ko);
                    if (TERMS == 3)
                        ldsm_x4(al, base + TILE_B + (uint32_t)(wm + mt * 16) * 80 + a_off + ko);
#pragma unroll
                    for (int nt = 0; nt < 4; nt++) {
                        mma_bf16(acc[mt][nt], ah, bh[nt]);
                        if (TERMS == 3) {
                            mma_bf16(acc[mt][nt], ah, bl[nt]);
                            mma_bf16(acc[mt][nt], al, bh[nt]);
                        }
                    }
                }
            }
        }
        if (c + 1 < nch) {
            char* dst = sm + ((c + 1) & 1) * BUF_B;
#pragma unroll
            for (int it = 0; it < NIT; it++) {
                const int idx = (it << 8) + tid;
                const int t = (TERMS == 3) ? (idx >> 9) : ((idx >> 9) * 2);
                const int r = (idx >> 2) & 127;
                const int s = idx & 3;
                *(uint4*)(dst + t * TILE_B + r * 80 + s * 16) = g[it];
            }
        }
        __syncthreads();
    }

#pragma unroll
    for (int mt = 0; mt < 4; mt++) {
        const int row0 = bm + wm + mt * 16 + (lane >> 2);
#pragma unroll
        for (int nt = 0; nt < 4; nt++) {
            const int col = bn + wn + nt * 8 + (lane & 3) * 2;
#pragma unroll
            for (int half = 0; half < 2; half++) {
                const int row = row0 + half * 8;
                float vx = acc[mt][nt][half * 2] * alpha;
                float vy = acc[mt][nt][half * 2 + 1] * alpha;
                if (Oh) {
                    uint32_t hp, lp;
                    split2(vx, vy, hp, lp);
                    *(uint32_t*)(Oh + (size_t)row * N + col) = hp;
                    *(uint32_t*)(Ol + (size_t)row * N + col) = lp;
                } else {
                    if (bias) { vx += bias[col]; vy += bias[col + 1]; }
                    if (resid) {
                        float2 t = *(const float2*)(resid + (size_t)row * N + col);
                        vx += t.x; vy += t.y;
                    }
                    *(float2*)(C + (size_t)row * N + col) = make_float2(vx, vy);
                }
            }
        }
    }
}

// ================================================================
// FUSED scores + softmax (validated R7). 144 B row stride.
// ================================================================
#define FS_QSP  4608
#define FS_QT   (2 * FS_QSP)
#define FS_KSP  18432
#define FS_KT   (2 * FS_KSP)
#define FS_SROW 4128
#define FS_SMEM (FS_QT + 2 * FS_KT + 32 * FS_SROW)   // 215040

__global__ void __launch_bounds__(256, 1) fused_attn_probs()
{
    extern __shared__ char sm[];
    const int tid = threadIdx.x;
    const int lane = tid & 31;
    const int wid = tid >> 5;
    const int z = blockIdx.y;
    const int b = z >> 4;
    const int h = z & 15;
    const int q0 = b * NC_ + blockIdx.x * 32;
    const int kb = b * NS_;

    char* smQ = sm;
    char* smK = sm + FS_QT;
    char* smS = sm + FS_QT + 2 * FS_KT;
    const uint32_t uQ = smem_u32(smQ);
    const uint32_t uK = smem_u32(smK);

#pragma unroll
    for (int it = 0; it < 2; it++) {
        const int idx = (it << 8) + tid;
        const int sp = idx >> 8;
        const int r = (idx >> 3) & 31;
        const int s = idx & 7;
        const __nv_bfloat16* src = sp ? g_ql : g_qh;
        uint4 v = *(const uint4*)(src + (size_t)(q0 + r) * INNER_ + h * 64 + s * 8);
        *(uint4*)(smQ + sp * FS_QSP + r * 144 + s * 16) = v;
    }
#pragma unroll
    for (int it = 0; it < 8; it++) {
        const int idx = (it << 8) + tid;
        const int sp = idx >> 10;
        const int r = (idx >> 3) & 127;
        const int s = idx & 7;
        const __nv_bfloat16* src = sp ? g_kl : g_kh;
        uint4 v = *(const uint4*)(src + (size_t)(kb + r) * INNER_ + h * 64 + s * 8);
        *(uint4*)(smK + sp * FS_KSP + r * 144 + s * 16) = v;
    }
    __syncthreads();

    const int wm = (wid >> 2) * 16;
    const int wn = (wid & 3) * 32;
    const uint32_t a_off = (uint32_t)(lane & 15) * 144 + (uint32_t)(lane >> 4) * 16;
    const uint32_t b_off = (uint32_t)(lane & 7) * 144 + (uint32_t)((lane >> 3) & 1) * 16;

    for (int kc = 0; kc < 8; kc++) {
        uint4 g[8];
        if (kc + 1 < 8) {
            const int krow = kb + (kc + 1) * 128;
#pragma unroll
            for (int it = 0; it < 8; it++) {
                const int idx = (it << 8) + tid;
                const int sp = idx >> 10;
                const int r = (idx >> 3) & 127;
                const int s = idx & 7;
                const __nv_bfloat16* src = sp ? g_kl : g_kh;
                g[it] = *(const uint4*)(src + (size_t)(krow + r) * INNER_ + h * 64 + s * 8);
            }
        }
        float acc[4][4];
#pragma unroll
        for (int nt = 0; nt < 4; nt++)
#pragma unroll
            for (int r = 0; r < 4; r++) acc[nt][r] = 0.f;

        const uint32_t kbuf = uK + (uint32_t)(kc & 1) * FS_KT;
#pragma unroll
        for (int kk = 0; kk < 4; kk++) {
            const uint32_t ko = kk * 32;
            uint32_t ah[4], al[4];
            ldsm_x4(ah, uQ + (uint32_t)wm * 144 + a_off + ko);
            ldsm_x4(al, uQ + FS_QSP + (uint32_t)wm * 144 + a_off + ko);
            uint32_t bh[4][2], bl[4][2];
#pragma unroll
            for (int nt = 0; nt < 4; nt++) {
                ldsm_x2(bh[nt], kbuf + (uint32_t)(wn + nt * 8) * 144 + b_off + ko);
                ldsm_x2(bl[nt], kbuf + FS_KSP + (uint32_t)(wn + nt * 8) * 144 + b_off + ko);
            }
#pragma unroll
            for (int nt = 0; nt < 4; nt++) {
                mma_bf16(acc[nt], ah, bh[nt]);
                mma_bf16(acc[nt], ah, bl[nt]);
                mma_bf16(acc[nt], al, bh[nt]);
            }
        }
#pragma unroll
        for (int nt = 0; nt < 4; nt++) {
            const int col = kc * 128 + wn + nt * 8 + (lane & 3) * 2;
#pragma unroll
            for (int half = 0; half < 2; half++) {
                const int row = wm + (lane >> 2) + half * 8;
                *(float2*)(smS + row * FS_SROW + col * 4) =
                    make_float2(acc[nt][half * 2], acc[nt][half * 2 + 1]);
            }
        }
        if (kc + 1 < 8) {
            char* dst = smK + ((kc + 1) & 1) * FS_KT;
#pragma unroll
            for (int it = 0; it < 8; it++) {
                const int idx = (it << 8) + tid;
                const int sp = idx >> 10;
                const int r = (idx >> 3) & 127;
                const int s = idx & 7;
                *(uint4*)(dst + sp * FS_KSP + r * 144 + s * 16) = g[it];
            }
        }
        __syncthreads();
    }

    char* gz = (char*)g_attn + ((((size_t)z << 12) + (size_t)blockIdx.x * 32) << 12);
#pragma unroll
    for (int rr = 0; rr < 4; rr++) {
        const int r = wid * 4 + rr;
        const char* rb = smS + r * FS_SROW + lane * 16;
        float4 v[8];
#pragma unroll
        for (int it = 0; it < 8; it++) v[it] = *(const float4*)(rb + it * 512);

        float m = -1e30f;
#pragma unroll
        for (int it = 0; it < 8; it++)
            m = fmaxf(m, fmaxf(fmaxf(v[it].x, v[it].y), fmaxf(v[it].z, v[it].w)));
#pragma unroll
        for (int o = 16; o; o >>= 1) m = fmaxf(m, __shfl_xor_sync(0xffffffffu, m, o));

        float s = 0.f;
#pragma unroll
        for (int it = 0; it < 8; it++) {
            v[it].x = __expf(v[it].x - m); v[it].y = __expf(v[it].y - m);
            v[it].z = __expf(v[it].z - m); v[it].w = __expf(v[it].w - m);
            s += (v[it].x + v[it].y) + (v[it].z + v[it].w);
        }
#pragma unroll
        for (int o = 16; o; o >>= 1) s += __shfl_xor_sync(0xffffffffu, s, o);
        const float inv = 1.f / s;

        char* grow = gz + (size_t)r * 4096;
#pragma unroll
        for (int it = 0; it < 8; it++) {
            const float x = v[it].x * inv, y = v[it].y * inv;
            const float zz = v[it].z * inv, w = v[it].w * inv;
            uint32_t h0, l0, h1, l1;
            split2(x, y, h0, l0);
            split2(zz, w, h1, l1);
            const int cofs = (it * 128 + lane * 4) * 2;
            *(uint2*)(grow + cofs) = make_uint2(h0, h1);
            *(uint2*)(grow + 2048 + cofs) = make_uint2(l0, l1);
        }
    }
}

// ================================================================
// attn_mean from hi/lo bf16 probs (exact path for output 1)
// ================================================================
__global__ void attn_mean_kernel(float* __restrict__ out2)
{
    const size_t idx = (size_t)blockIdx.x * 256 + threadIdx.x;
    const size_t e0 = idx << 2;
    const int b = (int)(e0 >> 22);
    const int q = (int)((e0 >> 10) & 4095);
    const int k = (int)(e0 & 1023);
    const __nv_bfloat16* pb = (const __nv_bfloat16*)g_attn;

    float s0 = 0.f, s1 = 0.f, s2 = 0.f, s3 = 0.f;
#pragma unroll
    for (int h = 0; h < H_; h++) {
        const size_t row = ((size_t)(b * H_ + h) << 12) + q;
        const __nv_bfloat16* ph = pb + row * 2048 + k;
        uint2 hv = *(const uint2*)ph;
        uint2 lv = *(const uint2*)(ph + 1024);
        float2 h0 = __bfloat1622float2(*(__nv_bfloat162*)&hv.x);
        float2 h1 = __bfloat1622float2(*(__nv_bfloat162*)&hv.y);
        float2 l0 = __bfloat1622float2(*(__nv_bfloat162*)&lv.x);
        float2 l1 = __bfloat1622float2(*(__nv_bfloat162*)&lv.y);
        s0 += h0.x + l0.x; s1 += h0.y + l0.y;
        s2 += h1.x + l1.x; s3 += h1.y + l1.y;
    }
    const float c = 1.0f / 16.0f;
    *(float4*)(out2 + e0) = make_float4(s0 * c, s1 * c, s2 * c, s3 * c);
}

// ================================================================
// av_mma: 1-TERM  av[q][h*64+d] = sum_k Ph[z][q][k] * Vth[z*64+d][k]
// 128x64 tile, K=1024 in 64-chunks dbuf. Reads P hi region only.
// ================================================================
#define AV_AT   18432
#define AV_BT   9216
#define AV_BUF  (AV_AT + AV_BT)     // 27648
#define AV_SMEM (2 * AV_BUF)        // 55296

__global__ void __launch_bounds__(256, 1) av_mma()
{
    extern __shared__ char sm[];
    const int tid = threadIdx.x;
    const int lane = tid & 31;
    const int wid = tid >> 5;
    const int by = blockIdx.x;
    const int z = blockIdx.y;
    const int b = z >> 4;
    const int h = z & 15;

    const int wm = (wid >> 2) * 64;
    const int wn = (wid & 3) * 16;
    const uint32_t sA = smem_u32(sm);
    const uint32_t a_off = (uint32_t)(lane & 15) * 144 + (uint32_t)(lane >> 4) * 16;
    const uint32_t b_off = (uint32_t)(lane & 7) * 144 + (uint32_t)((lane >> 3) & 1) * 16;

    const char* attn_bytes = (const char*)g_attn + ((((size_t)z << 12) + (size_t)by * 128) << 12);
    const __nv_bfloat16* vth = g_vth + (size_t)z * 64 * NS_;

    float acc[4][2][4];
#pragma unroll
    for (int mt = 0; mt < 4; mt++)
#pragma unroll
        for (int nt = 0; nt < 2; nt++)
#pragma unroll
            for (int r = 0; r < 4; r++) acc[mt][nt][r] = 0.f;

#define AV_LOAD_G(c_, gArr_)                                                          \
    {                                                                                 \
        const int cc = (c_);                                                          \
        _Pragma("unroll")                                                             \
        for (int it = 0; it < 6; it++) {                                              \
            const int item = (it << 8) + tid;                                         \
            if (item < 1024) {                                                        \
                const int r = item >> 3;                                              \
                const int s = item & 7;                                               \
                gArr_[it] = *(const uint4*)(attn_bytes + ((size_t)r << 12)            \
                              + cc * 128 + s * 16);                                   \
            } else {                                                                  \
                const int i2 = item - 1024;                                           \
                const int r = i2 >> 3;                                                \
                const int s = i2 & 7;                                                 \
                gArr_[it] = *(const uint4*)(vth + (size_t)r * NS_ + cc * 64 + s * 8); \
            }                                                                         \
        }                                                                             \
    }
#define AV_STORE_S(buf_, gArr_)                                                       \
    {                                                                                 \
        char* dst = sm + (buf_) * AV_BUF;                                             \
        _Pragma("unroll")                                                             \
        for (int it = 0; it < 6; it++) {                                              \
            const int item = (it << 8) + tid;                                         \
            if (item < 1024) {                                                        \
                const int r = item >> 3;                                              \
                const int s = item & 7;                                               \
                *(uint4*)(dst + r * 144 + s * 16) = gArr_[it];                        \
            } else {                                                                  \
                const int i2 = item - 1024;                                           \
                const int r = i2 >> 3;                                                \
                const int s = i2 & 7;                                                 \
                *(uint4*)(dst + AV_AT + r * 144 + s * 16) = gArr_[it];                \
            }                                                                         \
        }                                                                             \
    }

    {
        uint4 g[6];
        AV_LOAD_G(0, g);
        AV_STORE_S(0, g);
    }
    __syncthreads();

    for (int c = 0; c < 16; c++) {
        uint4 g[6];
        if (c + 1 < 16) AV_LOAD_G(c + 1, g);
        {
            const uint32_t base = sA + (uint32_t)(c & 1) * AV_BUF;
#pragma unroll
            for (int kk = 0; kk < 4; kk++) {
                const uint32_t ko = kk * 32;
                uint32_t bh[2][2];
#pragma unroll
                for (int nt = 0; nt < 2; nt++)
                    ldsm_x2(bh[nt], base + AV_AT + (uint32_t)(wn + nt * 8) * 144 + b_off + ko);
#pragma unroll
                for (int mt = 0; mt < 4; mt++) {
                    uint32_t ah[4];
                    ldsm_x4(ah, base + (uint32_t)(wm + mt * 16) * 144 + a_off + ko);
#pragma unroll
                    for (int nt = 0; nt < 2; nt++)
                        mma_bf16(acc[mt][nt], ah, bh[nt]);
                }
            }
        }
        if (c + 1 < 16) AV_STORE_S((c + 1) & 1, g);
        __syncthreads();
    }

#pragma unroll
    for (int mt = 0; mt < 4; mt++) {
        const int row0 = b * NC_ + by * 128 + wm + mt * 16 + (lane >> 2);
#pragma unroll
        for (int nt = 0; nt < 2; nt++) {
            const int col = h * 64 + wn + nt * 8 + (lane & 3) * 2;
#pragma unroll
            for (int half = 0; half < 2; half++) {
                const int row = row0 + half * 8;
                *(uint32_t*)(g_avh + (size_t)row * INNER_ + col) =
                    pack2(acc[mt][nt][half * 2], acc[mt][nt][half * 2 + 1]);
            }
        }
    }
}

// ================================================================
// fp32 -> bf16 hi/lo split
// ================================================================
__global__ void split_kernel(const float4* __restrict__ in,
                             uint2* __restrict__ oh, uint2* __restrict__ ol, int n4)
{
    const int i = blockIdx.x * 256 + threadIdx.x;
    if (i >= n4) return;
    float4 v = in[i];
    __align__(8) __nv_bfloat16 h[4], l[4];
    const float f[4] = {v.x, v.y, v.z, v.w};
#pragma unroll
    for (int j = 0; j < 4; j++) {
        h[j] = __float2bfloat16(f[j]);
        l[j] = __float2bfloat16(f[j] - __bfloat162float(h[j]));
    }
    oh[i] = *(uint2*)h;
    ol[i] = *(uint2*)l;
}

// ================================================================
// Transpose + split weights: fp32 [R][Ncol] -> bf16 [Ncol][R] hi/lo
// ================================================================
__global__ void tsplit_kernel(const float* __restrict__ in,
                              __nv_bfloat16* __restrict__ oh,
                              __nv_bfloat16* __restrict__ ol, int R, int Ncol)
{
    __shared__ float t[32][33];
    const int bx = blockIdx.x * 32, by = blockIdx.y * 32;
    const int tx = threadIdx.x, ty = threadIdx.y;
#pragma unroll
    for (int i = 0; i < 32; i += 8)
        t[ty + i][tx] = in[(size_t)(by + ty + i) * Ncol + bx + tx];
    __syncthreads();
#pragma unroll
    for (int i = 0; i < 32; i += 8) {
        const float v = t[tx][ty + i];
        const size_t o = (size_t)(bx + ty + i) * R + by + tx;
        __nv_bfloat16 h = __float2bfloat16(v);
        oh[o] = h;
        ol[o] = __float2bfloat16(v - __bfloat162float(h));
    }
}

// ================================================================
// V^T split (hi only — AV is 1-term now)
// ================================================================
__global__ void vtsplit_kernel()
{
    __shared__ float t[32][33];
    const int b = blockIdx.z;
    const int bx = blockIdx.x * 32;
    const int by = blockIdx.y * 32;
    const int tx = threadIdx.x, ty = threadIdx.y;
    const float* in = g_v + (size_t)b * NS_ * INNER_;
#pragma unroll
    for (int i = 0; i < 32; i += 8)
        t[ty + i][tx] = in[(size_t)(by + ty + i) * INNER_ + bx + tx];
    __syncthreads();
#pragma unroll
    for (int i = 0; i < 32; i += 8) {
        const float v = t[tx][ty + i];
        g_vth[(size_t)(b * 1024 + bx + ty + i) * NS_ + by + tx] = __float2bfloat16(v);
    }
}

// ================================================================
// LayerNorm
// ================================================================
__global__ void ln_kernel(const float* __restrict__ gamma,
                          const float* __restrict__ beta,
                          float* __restrict__ out)
{
    __shared__ float reds[9];
    __shared__ float redq[9];
    const size_t row = blockIdx.x;
    const int tid = threadIdx.x;

    float4 x = reinterpret_cast<const float4*>(g_x + row * CD_)[tid];
    float s = x.x + x.y + x.z + x.w;
    float q = x.x * x.x + x.y * x.y + x.z * x.z + x.w * x.w;
#pragma unroll
    for (int o = 16; o; o >>= 1) {
        s += __shfl_xor_sync(0xffffffffu, s, o);
        q += __shfl_xor_sync(0xffffffffu, q, o);
    }
    if ((tid & 31) == 0) { reds[tid >> 5] = s; redq[tid >> 5] = q; }
    __syncthreads();
    if (tid == 0) {
        float ss = 0.f, qq = 0.f;
#pragma unroll
        for (int i = 0; i < 8; i++) { ss += reds[i]; qq += redq[i]; }
        reds[8] = ss; redq[8] = qq;
    }
    __syncthreads();
    const float mu = reds[8] * (1.0f / 1024.0f);
    const float var = redq[8] * (1.0f / 1024.0f) - mu * mu;
    const float rstd = rsqrtf(var + LN_EPS);

    float4 g = reinterpret_cast<const float4*>(gamma)[tid];
    float4 bb = reinterpret_cast<const float4*>(beta)[tid];
    float4 r;
    r.x = (x.x - mu) * rstd * g.x + bb.x;
    r.y = (x.y - mu) * rstd * g.y + bb.y;
    r.z = (x.z - mu) * rstd * g.z + bb.z;
    r.w = (x.w - mu) * rstd * g.w + bb.w;
    reinterpret_cast<float4*>(out + row * CD_)[tid] = r;
}

// ================================================================
extern "C" void kernel_launch(void* const* d_in, const int* in_sizes, int n_in,
                              void* d_out, int out_size)
{
    const float* content = (const float*)d_in[0];
    const float* style   = (const float*)d_in[1];
    const float* Wq      = (const float*)d_in[2];
    const float* Wk      = (const float*)d_in[3];
    const float* Wv      = (const float*)d_in[4];
    const float* Wo      = (const float*)d_in[5];
    const float* bo      = (const float*)d_in[6];
    const float* gamma   = (const float*)d_in[7];
    const float* beta    = (const float*)d_in[8];
    float* out = (float*)d_out;
    float* out_attn = out + (size_t)B_ * NC_ * CD_;

    cudaFuncSetAttribute(gemm_mma<3>, cudaFuncAttributeMaxDynamicSharedMemorySize, GSMEM_B);
    cudaFuncSetAttribute(gemm_mma<1>, cudaFuncAttributeMaxDynamicSharedMemorySize, GSMEM_B);
    cudaFuncSetAttribute(fused_attn_probs, cudaFuncAttributeMaxDynamicSharedMemorySize, FS_SMEM);
    cudaFuncSetAttribute(av_mma, cudaFuncAttributeMaxDynamicSharedMemorySize, AV_SMEM);

    float *p_v, *p_x;
    __nv_bfloat16 *p_chi, *p_clo, *p_shi, *p_slo, *p_avh;
    __nv_bfloat16 *p_qh, *p_ql, *p_kh, *p_kl;
    __nv_bfloat16 *p_wqh, *p_wql, *p_wkh, *p_wkl, *p_wvh, *p_wvl, *p_woh;
    cudaGetSymbolAddress((void**)&p_v,   g_v);
    cudaGetSymbolAddress((void**)&p_x,   g_x);
    cudaGetSymbolAddress((void**)&p_chi, g_c_hi);
    cudaGetSymbolAddress((void**)&p_clo, g_c_lo);
    cudaGetSymbolAddress((void**)&p_shi, g_s_hi);
    cudaGetSymbolAddress((void**)&p_slo, g_s_lo);
    cudaGetSymbolAddress((void**)&p_qh,  g_qh);
    cudaGetSymbolAddress((void**)&p_ql,  g_ql);
    cudaGetSymbolAddress((void**)&p_kh,  g_kh);
    cudaGetSymbolAddress((void**)&p_kl,  g_kl);
    cudaGetSymbolAddress((void**)&p_avh, g_avh);
    cudaGetSymbolAddress((void**)&p_wqh, g_wqt_hi);
    cudaGetSymbolAddress((void**)&p_wql, g_wqt_lo);
    cudaGetSymbolAddress((void**)&p_wkh, g_wkt_hi);
    cudaGetSymbolAddress((void**)&p_wkl, g_wkt_lo);
    cudaGetSymbolAddress((void**)&p_wvh, g_wvt_hi);
    cudaGetSymbolAddress((void**)&p_wvl, g_wvt_lo);
    cudaGetSymbolAddress((void**)&p_woh, g_wot_hi);

    // 0) splits
    split_kernel<<<(B_ * NC_ * CD_ / 4 + 255) / 256, 256>>>(
        (const float4*)content, (uint2*)p_chi, (uint2*)p_clo, B_ * NC_ * CD_ / 4);
    split_kernel<<<(B_ * NS_ * SD_ / 4 + 255) / 256, 256>>>(
        (const float4*)style, (uint2*)p_shi, (uint2*)p_slo, B_ * NS_ * SD_ / 4);
    tsplit_kernel<<<dim3(32, 32), dim3(32, 8)>>>(Wq, p_wqh, p_wql, CD_, INNER_);
    tsplit_kernel<<<dim3(32, 24), dim3(32, 8)>>>(Wk, p_wkh, p_wkl, SD_, INNER_);
    tsplit_kernel<<<dim3(32, 24), dim3(32, 8)>>>(Wv, p_wvh, p_wvl, SD_, INNER_);
    // Wo: only hi needed (O-proj is 1-term). The lo output is written into g_ql,
    // which Q-proj overwrites afterward on the same stream — ordering makes it safe.
    tsplit_kernel<<<dim3(32, 32), dim3(32, 8)>>>(Wo, p_woh, p_ql /*discard*/, INNER_, CD_);

    // 1) Q proj -> bf16 hi/lo (pre-scaled 1/8)
    gemm_mma<3><<<dim3(INNER_ / 128, B_ * NC_ / 128), 256, GSMEM_B>>>(
        p_chi, p_clo, p_wqh, p_wql, nullptr, p_qh, p_ql,
        B_ * NC_, INNER_, CD_, nullptr, nullptr, 0.125f);
    // 2) K proj -> bf16 hi/lo
    gemm_mma<3><<<dim3(INNER_ / 128, B_ * NS_ / 128), 256, GSMEM_B>>>(
        p_shi, p_slo, p_wkh, p_wkl, nullptr, p_kh, p_kl,
        B_ * NS_, INNER_, SD_, nullptr, nullptr, 1.0f);
    // 3) V proj -> fp32, then per-head transpose (hi only)
    gemm_mma<3><<<dim3(INNER_ / 128, B_ * NS_ / 128), 256, GSMEM_B>>>(
        p_shi, p_slo, p_wvh, p_wvl, p_v, nullptr, nullptr,
        B_ * NS_, INNER_, SD_, nullptr, nullptr, 1.0f);
    vtsplit_kernel<<<dim3(32, 32, B_), dim3(32, 8)>>>();

    // 4) FUSED scores + softmax -> probs bf16 hi/lo in g_attn
    fused_attn_probs<<<dim3(NC_ / 32, B_ * H_), 256, FS_SMEM>>>();
    // 5) head-mean -> second output (hi+lo, exact)
    attn_mean_kernel<<<B_ * NC_ * NS_ / 4 / 256, 256>>>(out_attn);
    // 6) av = Ph @ Vh (1-term) -> bf16 hi
    av_mma<<<dim3(NC_ / 128, B_ * H_), 256, AV_SMEM>>>();
    // 7) O proj (1-term) + bias + residual
    gemm_mma<1><<<dim3(CD_ / 128, B_ * NC_ / 128), 256, GSMEM_B>>>(
        p_avh, nullptr, p_woh, nullptr, p_x, nullptr, nullptr,
        B_ * NC_, CD_, INNER_, bo, content, 1.0f);
    // 8) LayerNorm -> first output
    ln_kernel<<<B_ * NC_, 256>>>(gamma, beta, out);
}

// round 11
// speedup vs baseline: 2.6779x; 1.0070x over previous
#include <cuda_runtime.h>
#include <cuda_bf16.h>
#include <cuda_fp16.h>
#include <math.h>
#include <stdint.h>

#define B_    4
#define NC_   4096
#define NS_   1024
#define CD_   1024
#define SD_   768
#define H_    16
#define D_    64
#define INNER_ 1024
#define LN_EPS 1e-5f

// ---------------- static device scratch ----------------
__device__ float g_attn[(size_t)B_ * H_ * NC_ * NS_];   // probs fp16 rows (2048 B/row used)
__device__ float g_x[(size_t)B_ * NC_ * CD_];
__device__ float g_v[(size_t)B_ * NS_ * INNER_];

__device__ __nv_bfloat16 g_c_hi[(size_t)B_ * NC_ * CD_];
__device__ __nv_bfloat16 g_c_lo[(size_t)B_ * NC_ * CD_];
__device__ __nv_bfloat16 g_s_hi[(size_t)B_ * NS_ * SD_];
__device__ __nv_bfloat16 g_s_lo[(size_t)B_ * NS_ * SD_];
__device__ __nv_bfloat16 g_qh[(size_t)B_ * NC_ * INNER_];   // Q (pre-scaled 1/8) hi/lo
__device__ __nv_bfloat16 g_ql[(size_t)B_ * NC_ * INNER_];
__device__ __nv_bfloat16 g_kh[(size_t)B_ * NS_ * INNER_];
__device__ __nv_bfloat16 g_kl[(size_t)B_ * NS_ * INNER_];
__device__ __half        g_vth[(size_t)B_ * INNER_ * NS_];  // V^T per head [z*64+d][s], fp16
__device__ __nv_bfloat16 g_avh[(size_t)B_ * NC_ * INNER_];  // attended, bf16

__device__ __nv_bfloat16 g_wqt_hi[INNER_ * CD_];
__device__ __nv_bfloat16 g_wqt_lo[INNER_ * CD_];
__device__ __nv_bfloat16 g_wkt_hi[INNER_ * SD_];
__device__ __nv_bfloat16 g_wkt_lo[INNER_ * SD_];
__device__ __nv_bfloat16 g_wvt_hi[INNER_ * SD_];
__device__ __nv_bfloat16 g_wvt_lo[INNER_ * SD_];
__device__ __nv_bfloat16 g_wot_hi[CD_ * INNER_];

// ================= helpers =================
__device__ __forceinline__ uint32_t smem_u32(const void* p) {
    uint32_t a;
    asm("{ .reg .u64 t; cvta.to.shared.u64 t, %1; cvt.u32.u64 %0, t; }" : "=r"(a) : "l"(p));
    return a;
}
__device__ __forceinline__ void ldsm_x4(uint32_t* f, uint32_t addr) {
    asm volatile("ldmatrix.sync.aligned.m8n8.x4.shared.b16 {%0,%1,%2,%3}, [%4];"
                 : "=r"(f[0]), "=r"(f[1]), "=r"(f[2]), "=r"(f[3]) : "r"(addr));
}
__device__ __forceinline__ void ldsm_x2(uint32_t* f, uint32_t addr) {
    asm volatile("ldmatrix.sync.aligned.m8n8.x2.shared.b16 {%0,%1}, [%2];"
                 : "=r"(f[0]), "=r"(f[1]) : "r"(addr));
}
__device__ __forceinline__ void mma_bf16(float* c, const uint32_t* a, const uint32_t* b) {
    asm volatile("mma.sync.aligned.m16n8k16.row.col.f32.bf16.bf16.f32 "
                 "{%0,%1,%2,%3}, {%4,%5,%6,%7}, {%8,%9}, {%0,%1,%2,%3};"
                 : "+f"(c[0]), "+f"(c[1]), "+f"(c[2]), "+f"(c[3])
                 : "r"(a[0]), "r"(a[1]), "r"(a[2]), "r"(a[3]), "r"(b[0]), "r"(b[1]));
}
__device__ __forceinline__ void mma_f16(float* c, const uint32_t* a, const uint32_t* b) {
    asm volatile("mma.sync.aligned.m16n8k16.row.col.f32.f16.f16.f32 "
                 "{%0,%1,%2,%3}, {%4,%5,%6,%7}, {%8,%9}, {%0,%1,%2,%3};"
                 : "+f"(c[0]), "+f"(c[1]), "+f"(c[2]), "+f"(c[3])
                 : "r"(a[0]), "r"(a[1]), "r"(a[2]), "r"(a[3]), "r"(b[0]), "r"(b[1]));
}
__device__ __forceinline__ void split2(float x, float y, uint32_t& hp, uint32_t& lp) {
    __nv_bfloat16 hx = __float2bfloat16(x), hy = __float2bfloat16(y);
    hp = ((uint32_t)*(uint16_t*)&hy << 16) | *(uint16_t*)&hx;
    __nv_bfloat16 lx = __float2bfloat16(x - __bfloat162float(hx));
    __nv_bfloat16 ly = __float2bfloat16(y - __bfloat162float(hy));
    lp = ((uint32_t)*(uint16_t*)&ly << 16) | *(uint16_t*)&lx;
}
__device__ __forceinline__ uint32_t pack2(float x, float y) {
    __nv_bfloat16 hx = __float2bfloat16(x), hy = __float2bfloat16(y);
    return ((uint32_t)*(uint16_t*)&hy << 16) | *(uint16_t*)&hx;
}
__device__ __forceinline__ uint32_t packh2(float x, float y) {
    __half2 t = __floats2half2_rn(x, y);
    return *(uint32_t*)&t;
}

// ================================================================
// Templated bf16-split GEMM (validated R9). TERMS=3 or 1.
// ================================================================
#define TILE_B   10240
#define BUF_B    (4 * TILE_B)
#define GSMEM_B  (2 * BUF_B)

template <int TERMS>
__global__ void __launch_bounds__(256, 1) gemm_mma(
    const __nv_bfloat16* __restrict__ Ah, const __nv_bfloat16* __restrict__ Al,
    const __nv_bfloat16* __restrict__ Bh, const __nv_bfloat16* __restrict__ Bl,
    float* __restrict__ C, __nv_bfloat16* __restrict__ Oh, __nv_bfloat16* __restrict__ Ol,
    int M, int N, int K,
    const float* __restrict__ bias, const float* __restrict__ resid, float alpha)
{
    extern __shared__ char sm[];
    const int tid = threadIdx.x;
    const int lane = tid & 31;
    const int wid = tid >> 5;
    const int bm = blockIdx.y * 128;
    const int bn = blockIdx.x * 128;
    const int nch = K >> 5;
    const int NIT = (TERMS == 3) ? 8 : 4;

    const int wm = (wid >> 2) * 64;
    const int wn = (wid & 3) * 32;

    const uint32_t sA = smem_u32(sm);
    const uint32_t a_off = (uint32_t)(lane & 15) * 80 + (uint32_t)(lane >> 4) * 16;
    const uint32_t b_off = (uint32_t)(lane & 7) * 80 + (uint32_t)((lane >> 3) & 1) * 16;

    float acc[4][4][4];
#pragma unroll
    for (int mt = 0; mt < 4; mt++)
#pragma unroll
        for (int nt = 0; nt < 4; nt++)
#pragma unroll
            for (int r = 0; r < 4; r++) acc[mt][nt][r] = 0.f;

#pragma unroll
    for (int it = 0; it < NIT; it++) {
        const int idx = (it << 8) + tid;
        const int t = (TERMS == 3) ? (idx >> 9) : ((idx >> 9) * 2);
        const int r = (idx >> 2) & 127;
        const int s = idx & 3;
        const __nv_bfloat16* src = (t == 0) ? Ah : (t == 1) ? Al : (t == 2) ? Bh : Bl;
        const int rb = (t < 2) ? bm : bn;
        uint4 v = *(const uint4*)(src + (size_t)(rb + r) * K + s * 8);
        *(uint4*)(sm + t * TILE_B + r * 80 + s * 16) = v;
    }
    __syncthreads();

    for (int c = 0; c < nch; c++) {
        uint4 g[8];
        if (c + 1 < nch) {
            const int ko = (c + 1) << 5;
#pragma unroll
            for (int it = 0; it < NIT; it++) {
                const int idx = (it << 8) + tid;
                const int t = (TERMS == 3) ? (idx >> 9) : ((idx >> 9) * 2);
                const int r = (idx >> 2) & 127;
                const int s = idx & 3;
                const __nv_bfloat16* src = (t == 0) ? Ah : (t == 1) ? Al : (t == 2) ? Bh : Bl;
                const int rb = (t < 2) ? bm : bn;
                g[it] = *(const uint4*)(src + (size_t)(rb + r) * K + ko + s * 8);
            }
        }
        {
            const uint32_t base = sA + (uint32_t)(c & 1) * BUF_B;
#pragma unroll
            for (int kk = 0; kk < 2; kk++) {
                const uint32_t ko = kk * 32;
                uint32_t bh[4][2], bl[4][2];
#pragma unroll
                for (int nt = 0; nt < 4; nt++) {
                    ldsm_x2(bh[nt], base + 2 * TILE_B + (uint32_t)(wn + nt * 8) * 80 + b_off + ko);
                    if (TERMS == 3)
                        ldsm_x2(bl[nt], base + 3 * TILE_B + (uint32_t)(wn + nt * 8) * 80 + b_off + ko);
                }
#pragma unroll
                for (int mt = 0; mt < 4; mt++) {
                    uint32_t ah[4], al[4];
                    ldsm_x4(ah, base + (uint32_t)(wm + mt * 16) * 80 + a_off + ko);
                    if (TERMS == 3)
                        ldsm_x4(al, base + TILE_B + (uint32_t)(wm + mt * 16) * 80 + a_off + ko);
#pragma unroll
                    for (int nt = 0; nt < 4; nt++) {
                        mma_bf16(acc[mt][nt], ah, bh[nt]);
                        if (TERMS == 3) {
                            mma_bf16(acc[mt][nt], ah, bl[nt]);
                            mma_bf16(acc[mt][nt], al, bh[nt]);
                        }
                    }
                }
            }
        }
        if (c + 1 < nch) {
            char* dst = sm + ((c + 1) & 1) * BUF_B;
#pragma unroll
            for (int it = 0; it < NIT; it++) {
                const int idx = (it << 8) + tid;
                const int t = (TERMS == 3) ? (idx >> 9) : ((idx >> 9) * 2);
                const int r = (idx >> 2) & 127;
                const int s = idx & 3;
                *(uint4*)(dst + t * TILE_B + r * 80 + s * 16) = g[it];
            }
        }
        __syncthreads();
    }

#pragma unroll
    for (int mt = 0; mt < 4; mt++) {
        const int row0 = bm + wm + mt * 16 + (lane >> 2);
#pragma unroll
        for (int nt = 0; nt < 4; nt++) {
            const int col = bn + wn + nt * 8 + (lane & 3) * 2;
#pragma unroll
            for (int half = 0; half < 2; half++) {
                const int row = row0 + half * 8;
                float vx = acc[mt][nt][half * 2] * alpha;
                float vy = acc[mt][nt][half * 2 + 1] * alpha;
                if (Oh) {
                    uint32_t hp, lp;
                    split2(vx, vy, hp, lp);
                    *(uint32_t*)(Oh + (size_t)row * N + col) = hp;
                    *(uint32_t*)(Ol + (size_t)row * N + col) = lp;
                } else {
                    if (bias) { vx += bias[col]; vy += bias[col + 1]; }
                    if (resid) {
                        float2 t = *(const float2*)(resid + (size_t)row * N + col);
                        vx += t.x; vy += t.y;
                    }
                    *(float2*)(C + (size_t)row * N + col) = make_float2(vx, vy);
                }
            }
        }
    }
}

// ================================================================
// FUSED scores + softmax + P·V.  per CTA = (z, 32 q rows), NS=1024.
// Phase 1: 3-term bf16-split QK^T into fp32 smem scores (stride 4128).
// Phase 2: exact fp32 softmax; probs fp16 -> own smem row (first 2048 B)
//          + global g_attn (2048 B rows).
// Phase 3: O = P(fp16) @ V^T(fp16). 64-k chunks (av_mma-validated layout:
//          144 B rows, kk<4, ko<=96). O -> g_avh bf16.
// ================================================================
#define FS_QSP  4608
#define FS_QT   (2 * FS_QSP)
#define FS_KSP  18432
#define FS_KT   (2 * FS_KSP)
#define FS_SROW 4128
#define FS_SMEM (FS_QT + 2 * FS_KT + 32 * FS_SROW)   // 215040

__global__ void __launch_bounds__(256, 1) fused_attn()
{
    extern __shared__ char sm[];
    const int tid = threadIdx.x;
    const int lane = tid & 31;
    const int wid = tid >> 5;
    const int z = blockIdx.y;
    const int b = z >> 4;
    const int h = z & 15;
    const int q0 = b * NC_ + blockIdx.x * 32;
    const int kb = b * NS_;

    char* smQ = sm;
    char* smK = sm + FS_QT;
    char* smS = sm + FS_QT + 2 * FS_KT;
    const uint32_t uQ = smem_u32(smQ);
    const uint32_t uK = smem_u32(smK);
    const uint32_t uS = smem_u32(smS);

    // ---- Phase 1: scores ----
#pragma unroll
    for (int it = 0; it < 2; it++) {
        const int idx = (it << 8) + tid;
        const int sp = idx >> 8;
        const int r = (idx >> 3) & 31;
        const int s = idx & 7;
        const __nv_bfloat16* src = sp ? g_ql : g_qh;
        uint4 v = *(const uint4*)(src + (size_t)(q0 + r) * INNER_ + h * 64 + s * 8);
        *(uint4*)(smQ + sp * FS_QSP + r * 144 + s * 16) = v;
    }
#pragma unroll
    for (int it = 0; it < 8; it++) {
        const int idx = (it << 8) + tid;
        const int sp = idx >> 10;
        const int r = (idx >> 3) & 127;
        const int s = idx & 7;
        const __nv_bfloat16* src = sp ? g_kl : g_kh;
        uint4 v = *(const uint4*)(src + (size_t)(kb + r) * INNER_ + h * 64 + s * 8);
        *(uint4*)(smK + sp * FS_KSP + r * 144 + s * 16) = v;
    }
    __syncthreads();

    const int wm = (wid >> 2) * 16;
    const int wn = (wid & 3) * 32;
    const uint32_t a_off = (uint32_t)(lane & 15) * 144 + (uint32_t)(lane >> 4) * 16;
    const uint32_t b_off = (uint32_t)(lane & 7) * 144 + (uint32_t)((lane >> 3) & 1) * 16;

    for (int kc = 0; kc < 8; kc++) {
        uint4 g[8];
        if (kc + 1 < 8) {
            const int krow = kb + (kc + 1) * 128;
#pragma unroll
            for (int it = 0; it < 8; it++) {
                const int idx = (it << 8) + tid;
                const int sp = idx >> 10;
                const int r = (idx >> 3) & 127;
                const int s = idx & 7;
                const __nv_bfloat16* src = sp ? g_kl : g_kh;
                g[it] = *(const uint4*)(src + (size_t)(krow + r) * INNER_ + h * 64 + s * 8);
            }
        }
        float acc[4][4];
#pragma unroll
        for (int nt = 0; nt < 4; nt++)
#pragma unroll
            for (int r = 0; r < 4; r++) acc[nt][r] = 0.f;

        const uint32_t kbuf = uK + (uint32_t)(kc & 1) * FS_KT;
#pragma unroll
        for (int kk = 0; kk < 4; kk++) {
            const uint32_t ko = kk * 32;
            uint32_t ah[4], al[4];
            ldsm_x4(ah, uQ + (uint32_t)wm * 144 + a_off + ko);
            ldsm_x4(al, uQ + FS_QSP + (uint32_t)wm * 144 + a_off + ko);
            uint32_t bh[4][2], bl[4][2];
#pragma unroll
            for (int nt = 0; nt < 4; nt++) {
                ldsm_x2(bh[nt], kbuf + (uint32_t)(wn + nt * 8) * 144 + b_off + ko);
                ldsm_x2(bl[nt], kbuf + FS_KSP + (uint32_t)(wn + nt * 8) * 144 + b_off + ko);
            }
#pragma unroll
            for (int nt = 0; nt < 4; nt++) {
                mma_bf16(acc[nt], ah, bh[nt]);
                mma_bf16(acc[nt], ah, bl[nt]);
                mma_bf16(acc[nt], al, bh[nt]);
            }
        }
#pragma unroll
        for (int nt = 0; nt < 4; nt++) {
            const int col = kc * 128 + wn + nt * 8 + (lane & 3) * 2;
#pragma unroll
            for (int half = 0; half < 2; half++) {
                const int row = wm + (lane >> 2) + half * 8;
                *(float2*)(smS + row * FS_SROW + col * 4) =
                    make_float2(acc[nt][half * 2], acc[nt][half * 2 + 1]);
            }
        }
        if (kc + 1 < 8) {
            char* dst = smK + ((kc + 1) & 1) * FS_KT;
#pragma unroll
            for (int it = 0; it < 8; it++) {
                const int idx = (it << 8) + tid;
                const int sp = idx >> 10;
                const int r = (idx >> 3) & 127;
                const int s = idx & 7;
                *(uint4*)(dst + sp * FS_KSP + r * 144 + s * 16) = g[it];
            }
        }
        __syncthreads();
    }

    // ---- Phase 2: softmax; probs fp16 to own smem rows + global ----
    char* gz = (char*)g_attn + (((size_t)z << 12) + (size_t)blockIdx.x * 32) * 2048;
#pragma unroll
    for (int rr = 0; rr < 4; rr++) {
        const int r = wid * 4 + rr;
        char* rb = smS + r * FS_SROW;
        float4 v[8];
#pragma unroll
        for (int it = 0; it < 8; it++) v[it] = *(const float4*)(rb + lane * 16 + it * 512);

        float m = -1e30f;
#pragma unroll
        for (int it = 0; it < 8; it++)
            m = fmaxf(m, fmaxf(fmaxf(v[it].x, v[it].y), fmaxf(v[it].z, v[it].w)));
#pragma unroll
        for (int o = 16; o; o >>= 1) m = fmaxf(m, __shfl_xor_sync(0xffffffffu, m, o));

        float s = 0.f;
#pragma unroll
        for (int it = 0; it < 8; it++) {
            v[it].x = __expf(v[it].x - m); v[it].y = __expf(v[it].y - m);
            v[it].z = __expf(v[it].z - m); v[it].w = __expf(v[it].w - m);
            s += (v[it].x + v[it].y) + (v[it].z + v[it].w);
        }
#pragma unroll
        for (int o = 16; o; o >>= 1) s += __shfl_xor_sync(0xffffffffu, s, o);
        const float inv = 1.f / s;

        char* grow = gz + (size_t)r * 2048;
#pragma unroll
        for (int it = 0; it < 8; it++) {
            uint2 p = make_uint2(packh2(v[it].x * inv, v[it].y * inv),
                                 packh2(v[it].z * inv, v[it].w * inv));
            const int cofs = (it * 128 + lane * 4) * 2;
            *(uint2*)(rb + cofs) = p;       // own smem row (first 2048 B)
            *(uint2*)(grow + cofs) = p;     // global
        }
    }
    __syncthreads();

    // ---- Phase 3: O = P @ V^T  (64-k chunks, av_mma-validated layout) ----
    const __half* vth = g_vth + (size_t)z * 64 * NS_;
    const int wd = (wid & 3) * 16;
    const uint32_t ap_off = (uint32_t)(lane & 15) * FS_SROW + (uint32_t)(lane >> 4) * 16;

    float acco[2][4];
#pragma unroll
    for (int nt = 0; nt < 2; nt++)
#pragma unroll
        for (int r = 0; r < 4; r++) acco[nt][r] = 0.f;

    // V chunk: 64 rows x 64 fp16 (128 B) -> 512 uint4 items, 2 iterations
#define FV_LOAD(c_, gArr_)                                                            \
    {                                                                                 \
        _Pragma("unroll")                                                             \
        for (int it = 0; it < 2; it++) {                                              \
            const int idx = (it << 8) + tid;                                          \
            const int r = idx >> 3;                                                   \
            const int s = idx & 7;                                                    \
            gArr_[it] = *(const uint4*)(vth + (size_t)r * NS_ + (c_) * 64 + s * 8);   \
        }                                                                             \
    }
#define FV_STORE(buf_, gArr_)                                                         \
    {                                                                                 \
        char* dst = smK + (buf_) * FS_KT;                                             \
        _Pragma("unroll")                                                             \
        for (int it = 0; it < 2; it++) {                                              \
            const int idx = (it << 8) + tid;                                          \
            const int r = idx >> 3;                                                   \
            const int s = idx & 7;                                                    \
            *(uint4*)(dst + r * 144 + s * 16) = gArr_[it];                            \
        }                                                                             \
    }

    {
        uint4 g[2];
        FV_LOAD(0, g);
        FV_STORE(0, g);
    }
    __syncthreads();

    for (int c = 0; c < 16; c++) {
        uint4 g[2];
        if (c + 1 < 16) FV_LOAD(c + 1, g);
        {
            const uint32_t vbuf = uK + (uint32_t)(c & 1) * FS_KT;
#pragma unroll
            for (int kk = 0; kk < 4; kk++) {
                const uint32_t ko = kk * 32;   // 16 fp16 = 32 B
                uint32_t ah[4];
                ldsm_x4(ah, uS + (uint32_t)wm * FS_SROW + ap_off + (uint32_t)c * 128 + ko);
                uint32_t bh[2][2];
#pragma unroll
                for (int nt = 0; nt < 2; nt++)
                    ldsm_x2(bh[nt], vbuf + (uint32_t)(wd + nt * 8) * 144 + b_off + ko);
#pragma unroll
                for (int nt = 0; nt < 2; nt++)
                    mma_f16(acco[nt], ah, bh[nt]);
            }
        }
        if (c + 1 < 16) FV_STORE((c + 1) & 1, g);
        __syncthreads();
    }

    // epilogue: O 32x64 -> g_avh bf16
#pragma unroll
    for (int nt = 0; nt < 2; nt++) {
        const int col = h * 64 + wd + nt * 8 + (lane & 3) * 2;
#pragma unroll
        for (int half = 0; half < 2; half++) {
            const int row = q0 + wm + (lane >> 2) + half * 8;
            *(uint32_t*)(g_avh + (size_t)row * INNER_ + col) =
                pack2(acco[nt][half * 2], acco[nt][half * 2 + 1]);
        }
    }
}

// ================================================================
// attn_mean from fp16 probs (2048 B rows)
// ================================================================
__global__ void attn_mean_kernel(float* __restrict__ out2)
{
    const size_t idx = (size_t)blockIdx.x * 256 + threadIdx.x;
    const size_t e0 = idx << 2;
    const int b = (int)(e0 >> 22);
    const int q = (int)((e0 >> 10) & 4095);
    const int k = (int)(e0 & 1023);
    const __half* pb = (const __half*)g_attn;

    float s0 = 0.f, s1 = 0.f, s2 = 0.f, s3 = 0.f;
#pragma unroll
    for (int h = 0; h < H_; h++) {
        const size_t row = ((size_t)(b * H_ + h) << 12) + q;
        uint2 hv = *(const uint2*)(pb + row * 1024 + k);
        float2 h0 = __half22float2(*(__half2*)&hv.x);
        float2 h1 = __half22float2(*(__half2*)&hv.y);
        s0 += h0.x; s1 += h0.y; s2 += h1.x; s3 += h1.y;
    }
    const float c = 1.0f / 16.0f;
    *(float4*)(out2 + e0) = make_float4(s0 * c, s1 * c, s2 * c, s3 * c);
}

// ================================================================
// fp32 -> bf16 hi/lo split
// ================================================================
__global__ void split_kernel(const float4* __restrict__ in,
                             uint2* __restrict__ oh, uint2* __restrict__ ol, int n4)
{
    const int i = blockIdx.x * 256 + threadIdx.x;
    if (i >= n4) return;
    float4 v = in[i];
    __align__(8) __nv_bfloat16 h[4], l[4];
    const float f[4] = {v.x, v.y, v.z, v.w};
#pragma unroll
    for (int j = 0; j < 4; j++) {
        h[j] = __float2bfloat16(f[j]);
        l[j] = __float2bfloat16(f[j] - __bfloat162float(h[j]));
    }
    oh[i] = *(uint2*)h;
    ol[i] = *(uint2*)l;
}

// ================================================================
// Transpose + split weights: fp32 [R][Ncol] -> bf16 [Ncol][R] hi/lo
// ================================================================
__global__ void tsplit_kernel(const float* __restrict__ in,
                              __nv_bfloat16* __restrict__ oh,
                              __nv_bfloat16* __restrict__ ol, int R, int Ncol)
{
    __shared__ float t[32][33];
    const int bx = blockIdx.x * 32, by = blockIdx.y * 32;
    const int tx = threadIdx.x, ty = threadIdx.y;
#pragma unroll
    for (int i = 0; i < 32; i += 8)
        t[ty + i][tx] = in[(size_t)(by + ty + i) * Ncol + bx + tx];
    __syncthreads();
#pragma unroll
    for (int i = 0; i < 32; i += 8) {
        const float v = t[tx][ty + i];
        const size_t o = (size_t)(bx + ty + i) * R + by + tx;
        __nv_bfloat16 h = __float2bfloat16(v);
        oh[o] = h;
        ol[o] = __float2bfloat16(v - __bfloat162float(h));
    }
}

// ================================================================
// V^T to fp16
// ================================================================
__global__ void vtsplit_kernel()
{
    __shared__ float t[32][33];
    const int b = blockIdx.z;
    const int bx = blockIdx.x * 32;
    const int by = blockIdx.y * 32;
    const int tx = threadIdx.x, ty = threadIdx.y;
    const float* in = g_v + (size_t)b * NS_ * INNER_;
#pragma unroll
    for (int i = 0; i < 32; i += 8)
        t[ty + i][tx] = in[(size_t)(by + ty + i) * INNER_ + bx + tx];
    __syncthreads();
#pragma unroll
    for (int i = 0; i < 32; i += 8) {
        const float v = t[tx][ty + i];
        g_vth[(size_t)(b * 1024 + bx + ty + i) * NS_ + by + tx] = __float2half_rn(v);
    }
}

// ================================================================
// LayerNorm
// ================================================================
__global__ void ln_kernel(const float* __restrict__ gamma,
                          const float* __restrict__ beta,
                          float* __restrict__ out)
{
    __shared__ float reds[9];
    __shared__ float redq[9];
    const size_t row = blockIdx.x;
    const int tid = threadIdx.x;

    float4 x = reinterpret_cast<const float4*>(g_x + row * CD_)[tid];
    float s = x.x + x.y + x.z + x.w;
    float q = x.x * x.x + x.y * x.y + x.z * x.z + x.w * x.w;
#pragma unroll
    for (int o = 16; o; o >>= 1) {
        s += __shfl_xor_sync(0xffffffffu, s, o);
        q += __shfl_xor_sync(0xffffffffu, q, o);
    }
    if ((tid & 31) == 0) { reds[tid >> 5] = s; redq[tid >> 5] = q; }
    __syncthreads();
    if (tid == 0) {
        float ss = 0.f, qq = 0.f;
#pragma unroll
        for (int i = 0; i < 8; i++) { ss += reds[i]; qq += redq[i]; }
        reds[8] = ss; redq[8] = qq;
    }
    __syncthreads();
    const float mu = reds[8] * (1.0f / 1024.0f);
    const float var = redq[8] * (1.0f / 1024.0f) - mu * mu;
    const float rstd = rsqrtf(var + LN_EPS);

    float4 g = reinterpret_cast<const float4*>(gamma)[tid];
    float4 bb = reinterpret_cast<const float4*>(beta)[tid];
    float4 r;
    r.x = (x.x - mu) * rstd * g.x + bb.x;
    r.y = (x.y - mu) * rstd * g.y + bb.y;
    r.z = (x.z - mu) * rstd * g.z + bb.z;
    r.w = (x.w - mu) * rstd * g.w + bb.w;
    reinterpret_cast<float4*>(out + row * CD_)[tid] = r;
}

// ================================================================
extern "C" void kernel_launch(void* const* d_in, const int* in_sizes, int n_in,
                              void* d_out, int out_size)
{
    const float* content = (const float*)d_in[0];
    const float* style   = (const float*)d_in[1];
    const float* Wq      = (const float*)d_in[2];
    const float* Wk      = (const float*)d_in[3];
    const float* Wv      = (const float*)d_in[4];
    const float* Wo      = (const float*)d_in[5];
    const float* bo      = (const float*)d_in[6];
    const float* gamma   = (const float*)d_in[7];
    const float* beta    = (const float*)d_in[8];
    float* out = (float*)d_out;
    float* out_attn = out + (size_t)B_ * NC_ * CD_;

    cudaFuncSetAttribute(gemm_mma<3>, cudaFuncAttributeMaxDynamicSharedMemorySize, GSMEM_B);
    cudaFuncSetAttribute(gemm_mma<1>, cudaFuncAttributeMaxDynamicSharedMemorySize, GSMEM_B);
    cudaFuncSetAttribute(fused_attn, cudaFuncAttributeMaxDynamicSharedMemorySize, FS_SMEM);

    float *p_x, *p_v;
    __nv_bfloat16 *p_chi, *p_clo, *p_shi, *p_slo, *p_avh;
    __nv_bfloat16 *p_qh, *p_ql, *p_kh, *p_kl;
    __nv_bfloat16 *p_wqh, *p_wql, *p_wkh, *p_wkl, *p_wvh, *p_wvl, *p_woh;
    cudaGetSymbolAddress((void**)&p_v,   g_v);
    cudaGetSymbolAddress((void**)&p_x,   g_x);
    cudaGetSymbolAddress((void**)&p_chi, g_c_hi);
    cudaGetSymbolAddress((void**)&p_clo, g_c_lo);
    cudaGetSymbolAddress((void**)&p_shi, g_s_hi);
    cudaGetSymbolAddress((void**)&p_slo, g_s_lo);
    cudaGetSymbolAddress((void**)&p_qh,  g_qh);
    cudaGetSymbolAddress((void**)&p_ql,  g_ql);
    cudaGetSymbolAddress((void**)&p_kh,  g_kh);
    cudaGetSymbolAddress((void**)&p_kl,  g_kl);
    cudaGetSymbolAddress((void**)&p_avh, g_avh);
    cudaGetSymbolAddress((void**)&p_wqh, g_wqt_hi);
    cudaGetSymbolAddress((void**)&p_wql, g_wqt_lo);
    cudaGetSymbolAddress((void**)&p_wkh, g_wkt_hi);
    cudaGetSymbolAddress((void**)&p_wkl, g_wkt_lo);
    cudaGetSymbolAddress((void**)&p_wvh, g_wvt_hi);
    cudaGetSymbolAddress((void**)&p_wvl, g_wvt_lo);
    cudaGetSymbolAddress((void**)&p_woh, g_wot_hi);

    // 0) splits
    split_kernel<<<(B_ * NC_ * CD_ / 4 + 255) / 256, 256>>>(
        (const float4*)content, (uint2*)p_chi, (uint2*)p_clo, B_ * NC_ * CD_ / 4);
    split_kernel<<<(B_ * NS_ * SD_ / 4 + 255) / 256, 256>>>(
        (const float4*)style, (uint2*)p_shi, (uint2*)p_slo, B_ * NS_ * SD_ / 4);
    tsplit_kernel<<<dim3(32, 32), dim3(32, 8)>>>(Wq, p_wqh, p_wql, CD_, INNER_);
    tsplit_kernel<<<dim3(32, 24), dim3(32, 8)>>>(Wk, p_wkh, p_wkl, SD_, INNER_);
    tsplit_kernel<<<dim3(32, 24), dim3(32, 8)>>>(Wv, p_wvh, p_wvl, SD_, INNER_);
    // Wo: only hi needed (1-term O-proj). lo lands in g_ql, overwritten by Q proj after.
    tsplit_kernel<<<dim3(32, 32), dim3(32, 8)>>>(Wo, p_woh, p_ql /*discard*/, INNER_, CD_);

    // 1) Q proj -> bf16 hi/lo (pre-scaled 1/8)
    gemm_mma<3><<<dim3(INNER_ / 128, B_ * NC_ / 128), 256, GSMEM_B>>>(
        p_chi, p_clo, p_wqh, p_wql, nullptr, p_qh, p_ql,
        B_ * NC_, INNER_, CD_, nullptr, nullptr, 0.125f);
    // 2) K proj -> bf16 hi/lo
    gemm_mma<3><<<dim3(INNER_ / 128, B_ * NS_ / 128), 256, GSMEM_B>>>(
        p_shi, p_slo, p_wkh, p_wkl, nullptr, p_kh, p_kl,
        B_ * NS_, INNER_, SD_, nullptr, nullptr, 1.0f);
    // 3) V proj -> fp32, then per-head transpose to fp16
    gemm_mma<3><<<dim3(INNER_ / 128, B_ * NS_ / 128), 256, GSMEM_B>>>(
        p_shi, p_slo, p_wvh, p_wvl, p_v, nullptr, nullptr,
        B_ * NS_, INNER_, SD_, nullptr, nullptr, 1.0f);
    vtsplit_kernel<<<dim3(32, 32, B_), dim3(32, 8)>>>();

    // 4) FUSED scores + softmax + P·V  -> probs fp16 in g_attn, av bf16 in g_avh
    fused_attn<<<dim3(NC_ / 32, B_ * H_), 256, FS_SMEM>>>();
    // 5) head-mean -> second output
    attn_mean_kernel<<<B_ * NC_ * NS_ / 4 / 256, 256>>>(out_attn);
    // 6) O proj (1-term) + bias + residual
    gemm_mma<1><<<dim3(CD_ / 128, B_ * NC_ / 128), 256, GSMEM_B>>>(
        p_avh, nullptr, p_woh, nullptr, p_x, nullptr, nullptr,
        B_ * NC_, CD_, INNER_, bo, content, 1.0f);
    // 7) LayerNorm -> first output
    ln_kernel<<<B_ * NC_, 256>>>(gamma, beta, out);
}